// round 10
// baseline (speedup 1.0000x reference)
#include <cuda_runtime.h>
#include <cuda_bf16.h>
#include <math.h>
#include <stdint.h>

#define NB 16
#define CT 1024
#define CS 512
#define CM 512
#define HH 64
#define WW 64
#define HW 4096
#define NP 256
#define NA 256

// ---------------- scratch (device globals; no allocation) ----------------
__device__ float g_heatacc[NB * HW];  // conv+1x1 fused accumulator
__device__ float g_heat[NB * HW];
__device__ float g_score[NB * HW];
__device__ int   g_idx[NB * NA];
__device__ float g_sampT[NB * NA * CT];
__device__ float g_sampS[NB * NA * CS];
__device__ float g_sal[NB * NA];
__device__ float g_ft[NB * NA * NP];
__device__ float g_fs[NB * NA * NP];
__device__ int   g_bd[NB * NA];
__device__ int   g_cnt[NB];
__device__ float g_gafd;
__device__ float g_abcd_b[NB];

// bf16 hi/lo split tensors for tensor-core conv
__device__ __align__(16) __nv_bfloat16 g_Thi[NB * HW * CT];      // [b][p][ci]
__device__ __align__(16) __nv_bfloat16 g_Tlo[NB * HW * CT];
__device__ __align__(16) __nv_bfloat16 g_Whi[9 * CM * CT];       // [tap][co][ci]
__device__ __align__(16) __nv_bfloat16 g_Wlo[9 * CM * CT];

// ---------------- sm_80-class PTX helpers (compile on compute_103) --------
__device__ __forceinline__ uint32_t smem_to_u32(const void* smem_ptr) {
    uint32_t addr;
    asm("{ .reg .u64 tmp; cvta.to.shared.u64 tmp, %1; cvt.u32.u64 %0, tmp; }"
        : "=r"(addr) : "l"(smem_ptr));
    return addr;
}
__device__ __forceinline__ void cp16(uint32_t dst, const void* src, bool ok) {
    int sz = ok ? 16 : 0;
    asm volatile("cp.async.cg.shared.global [%0], [%1], 16, %2;"
                 :: "r"(dst), "l"(src), "r"(sz) : "memory");
}
#define CP_COMMIT() asm volatile("cp.async.commit_group;" ::: "memory")
#define CP_WAIT1()  asm volatile("cp.async.wait_group 1;" ::: "memory")
#define CP_WAIT0()  asm volatile("cp.async.wait_group 0;" ::: "memory")

__device__ __forceinline__ void ldsm4(uint32_t* r, uint32_t addr) {
    asm volatile("ldmatrix.sync.aligned.m8n8.x4.shared.b16 {%0,%1,%2,%3}, [%4];"
                 : "=r"(r[0]), "=r"(r[1]), "=r"(r[2]), "=r"(r[3]) : "r"(addr));
}
__device__ __forceinline__ void mma16816(float* c, const uint32_t* a,
                                         uint32_t b0, uint32_t b1) {
    asm volatile(
        "mma.sync.aligned.m16n8k16.row.col.f32.bf16.bf16.f32 "
        "{%0,%1,%2,%3}, {%4,%5,%6,%7}, {%8,%9}, {%0,%1,%2,%3};"
        : "+f"(c[0]), "+f"(c[1]), "+f"(c[2]), "+f"(c[3])
        : "r"(a[0]), "r"(a[1]), "r"(a[2]), "r"(a[3]), "r"(b0), "r"(b1));
}

// ---------------- generic helpers ----------------
__device__ __forceinline__ float block_sum_256(float v, float* sh) {
#pragma unroll
    for (int o = 16; o; o >>= 1) v += __shfl_down_sync(0xffffffffu, v, o);
    __syncthreads();
    if ((threadIdx.x & 31) == 0) sh[threadIdx.x >> 5] = v;
    __syncthreads();
    if (threadIdx.x == 0) {
        float t = 0.f;
        for (int i = 0; i < 8; ++i) t += sh[i];
        sh[32] = t;
    }
    __syncthreads();
    return sh[32];
}

__device__ __forceinline__ float block_max_256(float v, float* sh) {
#pragma unroll
    for (int o = 16; o; o >>= 1) v = fmaxf(v, __shfl_down_sync(0xffffffffu, v, o));
    __syncthreads();
    if ((threadIdx.x & 31) == 0) sh[threadIdx.x >> 5] = v;
    __syncthreads();
    if (threadIdx.x == 0) {
        float t = sh[0];
        for (int i = 1; i < 8; ++i) t = fmaxf(t, sh[i]);
        sh[32] = t;
    }
    __syncthreads();
    return sh[32];
}

__device__ __forceinline__ void threefry2x32(unsigned k0, unsigned k1,
                                             unsigned x0, unsigned x1,
                                             unsigned& o0, unsigned& o1) {
    unsigned ks[3] = {k0, k1, k0 ^ k1 ^ 0x1BD11BDAu};
    x0 += ks[0];
    x1 += ks[1];
    const int R[5][4] = {{13, 15, 26, 6}, {17, 29, 16, 24}, {13, 15, 26, 6},
                         {17, 29, 16, 24}, {13, 15, 26, 6}};
#pragma unroll
    for (int g = 0; g < 5; ++g) {
#pragma unroll
        for (int q = 0; q < 4; ++q) {
            x0 += x1;
            int rr = R[g][q];
            x1 = (x1 << rr) | (x1 >> (32 - rr));
            x1 ^= x0;
        }
        x0 += ks[(g + 1) % 3];
        x1 += ks[(g + 2) % 3] + (unsigned)(g + 1);
    }
    o0 = x0;
    o1 = x1;
}

// ---------------- kernels ----------------
// zero heat accumulator + loss scalars (runs every launch; graph-safe)
__global__ void reset_kernel() {
    int i = blockIdx.x * blockDim.x + threadIdx.x;
    if (i < NB * HW) g_heatacc[i] = 0.f;
    if (i == 0) g_gafd = 0.f;
    if (i < NB) g_abcd_b[i] = 0.f;
}

// transpose + bf16 split of teacher feat: T[b][ci][p] -> Thi/Tlo[b][p][ci]
__global__ void tprep_kernel(const float* __restrict__ T) {
    __shared__ float tile[32][33];
    int b = blockIdx.z, p0 = blockIdx.x * 32, c0 = blockIdx.y * 32;
    int tx = threadIdx.x, ty = threadIdx.y;
    for (int i = ty; i < 32; i += 8)
        tile[i][tx] = T[((size_t)(b * CT + c0 + i)) * HW + p0 + tx];
    __syncthreads();
    for (int i = ty; i < 32; i += 8) {
        float v = tile[tx][i];
        __nv_bfloat16 h = __float2bfloat16(v);
        float hf = __bfloat162float(h);
        size_t o = ((size_t)b * HW + p0 + i) * CT + c0 + tx;
        g_Thi[o] = h;
        g_Tlo[o] = __float2bfloat16(v - hf);
    }
}

// weights split: W1[co][ci][tap] -> Whi/Wlo[tap][co][ci]
__global__ void wprep_kernel(const float* __restrict__ W1) {
    int idx = blockIdx.x * blockDim.x + threadIdx.x;
    if (idx >= 9 * CM * CT) return;
    int ci = idx & (CT - 1);
    int rest = idx >> 10;
    int co = rest & (CM - 1);
    int tap = rest >> 9;
    float w = W1[((size_t)co * CT + ci) * 9 + tap];
    __nv_bfloat16 h = __float2bfloat16(w);
    float hf = __bfloat162float(h);
    g_Whi[idx] = h;
    g_Wlo[idx] = __float2bfloat16(w - hf);
}

// conv1 (bf16x3 implicit GEMM via mma.sync) FUSED with the 1x1 conv:
// epilogue dots relu(conv1+b1) with w2 and atomically accumulates per-pixel.
// CTA: 256 threads, 128 px x 128 co. 2-stage cp.async pipeline (K sub-chunk
// = 32 ci), 2 CTAs per SM.
#define ROW2 80                        // 64B data + 16B pad
#define A_B2 (128 * ROW2)              // 10240
#define STAGE2 (4 * A_B2)              // Ahi,Alo,Bhi,Blo = 40960
__global__ __launch_bounds__(256, 2)
void convmma_kernel(const float* __restrict__ b1, const float* __restrict__ w2) {
    extern __shared__ char dsm[];
    uint32_t sb = smem_to_u32(dsm);
    int tid = threadIdx.x, lane = tid & 31, wid = tid >> 5;
    int co0 = blockIdx.x * 128;
    int pixtile = blockIdx.y;
    int bb = blockIdx.z;
    int y0 = pixtile * 2, p0 = pixtile * 128;
    int wm = wid & 3, wn = wid >> 2;

    float acc[2][8][4];
#pragma unroll
    for (int i = 0; i < 2; ++i)
#pragma unroll
        for (int j = 0; j < 8; ++j)
#pragma unroll
            for (int k = 0; k < 4; ++k) acc[i][j][k] = 0.f;

    // 288 sub-chunks: tap = cc>>5, ci0 = (cc&31)*32
    auto load_sub = [&](int cc, int s) {
        int tap = cc >> 5;
        int dy = tap / 3 - 1, dx = tap % 3 - 1;
        int ci0 = (cc & 31) * 32;
        uint32_t base = sb + (uint32_t)s * STAGE2;
#pragma unroll
        for (int i = 0; i < 2; ++i) {
            int u = i * 256 + tid;       // 0..511
            int r = u >> 2, seg = u & 3; // 128 rows x 4 16B-segs
            int ys = y0 + (r >> 6) + dy;
            int xs = (r & 63) + dx;
            bool ok = ((unsigned)ys < 64u) && ((unsigned)xs < 64u);
            int ysc = ok ? ys : 0, xsc = ok ? xs : 0;
            size_t g = ((size_t)(bb * HW + ysc * 64 + xsc)) * CT + ci0 + seg * 8;
            uint32_t off = (uint32_t)(r * ROW2 + seg * 16);
            cp16(base + off, g_Thi + g, ok);
            cp16(base + A_B2 + off, g_Tlo + g, ok);
        }
#pragma unroll
        for (int i = 0; i < 2; ++i) {
            int u = i * 256 + tid;
            int r = u >> 2, seg = u & 3;
            size_t g = ((size_t)(tap * CM + co0 + r)) * CT + ci0 + seg * 8;
            uint32_t off = (uint32_t)(r * ROW2 + seg * 16);
            cp16(base + 2 * A_B2 + off, g_Whi + g, true);
            cp16(base + 3 * A_B2 + off, g_Wlo + g, true);
        }
    };

    auto compute = [&](int s) {
        uint32_t Ah = sb + (uint32_t)s * STAGE2;
        uint32_t Al = Ah + A_B2;
        uint32_t Bh = Ah + 2 * A_B2;
        uint32_t Bl = Ah + 3 * A_B2;
#pragma unroll
        for (int ks = 0; ks < 2; ++ks) {
            uint32_t aH[2][4], aL[2][4];
#pragma unroll
            for (int t = 0; t < 2; ++t) {
                uint32_t ra = (uint32_t)((wm * 32 + t * 16 + (lane & 15)) * ROW2 +
                                         ks * 32 + (lane >> 4) * 16);
                ldsm4(aH[t], Ah + ra);
                ldsm4(aL[t], Al + ra);
            }
#pragma unroll
            for (int nt = 0; nt < 4; ++nt) {
                uint32_t rb = (uint32_t)((wn * 64 + nt * 16 + (lane & 15)) * ROW2 +
                                         ks * 32 + (lane >> 4) * 16);
                uint32_t bHf[4], bLf[4];
                ldsm4(bHf, Bh + rb);
                ldsm4(bLf, Bl + rb);
#pragma unroll
                for (int mi = 0; mi < 2; ++mi) {
                    mma16816(acc[mi][2 * nt], aH[mi], bHf[0], bHf[2]);
                    mma16816(acc[mi][2 * nt + 1], aH[mi], bHf[1], bHf[3]);
                    mma16816(acc[mi][2 * nt], aL[mi], bHf[0], bHf[2]);
                    mma16816(acc[mi][2 * nt + 1], aL[mi], bHf[1], bHf[3]);
                    mma16816(acc[mi][2 * nt], aH[mi], bLf[0], bLf[2]);
                    mma16816(acc[mi][2 * nt + 1], aH[mi], bLf[1], bLf[3]);
                }
            }
        }
    };

    load_sub(0, 0);
    CP_COMMIT();
#pragma unroll 1
    for (int cc = 0; cc < 288; ++cc) {
        int s = cc & 1;
        if (cc + 1 < 288) {
            load_sub(cc + 1, s ^ 1);
            CP_COMMIT();
            CP_WAIT1();
        } else {
            CP_WAIT0();
        }
        __syncthreads();
        compute(s);
        __syncthreads();
    }

    // fused epilogue: h = relu(acc + b1); heatacc[p] += sum_co h * w2[co]
    float hp[2][2] = {{0.f, 0.f}, {0.f, 0.f}};  // [mi][row-half]
#pragma unroll
    for (int mi = 0; mi < 2; ++mi) {
#pragma unroll
        for (int nt = 0; nt < 8; ++nt) {
            int co = co0 + wn * 64 + nt * 8 + (lane & 3) * 2;
            float bv0 = b1[co], bv1 = b1[co + 1];
            float w20 = w2[co], w21 = w2[co + 1];
            float h00 = fmaxf(acc[mi][nt][0] + bv0, 0.f);
            float h01 = fmaxf(acc[mi][nt][1] + bv1, 0.f);
            float h10 = fmaxf(acc[mi][nt][2] + bv0, 0.f);
            float h11 = fmaxf(acc[mi][nt][3] + bv1, 0.f);
            hp[mi][0] += h00 * w20 + h01 * w21;
            hp[mi][1] += h10 * w20 + h11 * w21;
        }
    }
#pragma unroll
    for (int mi = 0; mi < 2; ++mi) {
        int r0 = wm * 32 + mi * 16 + (lane >> 2);
        atomicAdd(&g_heatacc[bb * HW + p0 + r0], hp[mi][0]);
        atomicAdd(&g_heatacc[bb * HW + p0 + r0 + 8], hp[mi][1]);
    }
}

// softplus(acc + b2) -> heatmap (scratch + output)
__global__ void softplus_kernel(const float* __restrict__ b2,
                                float* __restrict__ out) {
    int i = blockIdx.x * 256 + threadIdx.x;
    float a = g_heatacc[i] + b2[0];
    float sp = fmaxf(a, 0.f) + log1pf(expf(-fabsf(a)));
    g_heat[i] = sp;
    out[3 + i] = sp;
}

// per-batch: normalize to prob, add JAX (partitionable threefry) Gumbel -> score
__global__ void score_kernel() {
    __shared__ float sh[33];
    int b = blockIdx.x;
    float s = 0.f;
    for (int p = threadIdx.x; p < HW; p += 256) s += g_heat[b * HW + p];
    float S = block_sum_256(s, sh);
    for (int p = threadIdx.x; p < HW; p += 256) {
        unsigned gi = (unsigned)(b * HW + p);
        unsigned o0, o1;
        threefry2x32(0u, 42u, 0u, gi, o0, o1);
        unsigned bits = o0 ^ o1;
        float f = __uint_as_float((bits >> 9) | 0x3f800000u) - 1.0f;
        float u = fmaxf(1e-8f, f * (1.0f - 1e-8f) + 1e-8f);
        float gum = -logf(-logf(u));
        g_score[gi] = logf(g_heat[gi] / (S + 1e-6f) + 1e-12f) + gum;
    }
}

// top-256 per batch via in-smem bitonic sort
__global__ void topk_kernel() {
    __shared__ float key[HW];
    __shared__ int val[HW];
    int b = blockIdx.x;
    for (int i = threadIdx.x; i < HW; i += blockDim.x) {
        key[i] = -g_score[b * HW + i];
        val[i] = i;
    }
    for (int k = 2; k <= HW; k <<= 1)
        for (int j = k >> 1; j > 0; j >>= 1) {
            __syncthreads();
            for (int i = threadIdx.x; i < HW; i += blockDim.x) {
                int p = i ^ j;
                if (p > i) {
                    bool up = ((i & k) == 0);
                    float ki = key[i], kp = key[p];
                    if ((ki > kp) == up) {
                        key[i] = kp;
                        key[p] = ki;
                        int t = val[i];
                        val[i] = val[p];
                        val[p] = t;
                    }
                }
            }
        }
    __syncthreads();
    for (int i = threadIdx.x; i < NA; i += blockDim.x) g_idx[b * NA + i] = val[i];
}

// bilinear sample == 0.25 * sum of 4 pixels with zero pad
__global__ void gather_kernel(const float* __restrict__ T,
                              const float* __restrict__ Sf) {
    int blk = blockIdx.x;
    int b = blk >> 8, n = blk & 255;
    int idx = g_idx[b * NA + n];
    int r = idx >> 6, c = idx & 63;
    bool rv = r > 0, cv = c > 0;
    int o11 = r * WW + c, o10 = o11 - 1, o01 = o11 - WW, o00 = o01 - 1;
    for (int ch = threadIdx.x; ch < CT; ch += blockDim.x) {
        const float* base = T + (size_t)(b * CT + ch) * HW;
        float s = base[o11];
        if (cv) s += base[o10];
        if (rv) {
            s += base[o01];
            if (cv) s += base[o00];
        }
        g_sampT[(size_t)(b * NA + n) * CT + ch] = 0.25f * s;
    }
    for (int ch = threadIdx.x; ch < CS; ch += blockDim.x) {
        const float* base = Sf + (size_t)(b * CS + ch) * HW;
        float s = base[o11];
        if (cv) s += base[o10];
        if (rv) {
            s += base[o01];
            if (cv) s += base[o00];
        }
        g_sampS[(size_t)(b * NA + n) * CS + ch] = 0.25f * s;
    }
    if (threadIdx.x == 0) {
        const float* base = g_heat + b * HW;
        float s = base[o11];
        if (cv) s += base[o10];
        if (rv) {
            s += base[o01];
            if (cv) s += base[o00];
        }
        g_sal[b * NA + n] = 0.25f * s;
    }
}

// [rows,C]@[C,256] + bias -> LayerNorm -> l2norm. 8 rows per block, thread = p.
template <int C>
__global__ void proj_kernel(const float* __restrict__ wmat,
                            const float* __restrict__ bias,
                            const float* __restrict__ gamma,
                            const float* __restrict__ beta) {
    __shared__ float sRow[8 * C];
    __shared__ float sh[33];
    const float* samp = (C == CT) ? g_sampT : g_sampS;
    float* outp = (C == CT) ? g_ft : g_fs;
    int a0 = blockIdx.x * 8;
    int p = threadIdx.x;
    for (int i = threadIdx.x; i < 8 * C; i += 256) sRow[i] = samp[(size_t)a0 * C + i];
    __syncthreads();
    float acc[8];
#pragma unroll
    for (int i = 0; i < 8; ++i) acc[i] = 0.f;
    for (int c = 0; c < C; ++c) {
        float w = wmat[(size_t)c * NP + p];
#pragma unroll
        for (int i = 0; i < 8; ++i) acc[i] += sRow[i * C + c] * w;
    }
    float bi = bias[p], ga = gamma[p], be = beta[p];
#pragma unroll 1
    for (int i = 0; i < 8; ++i) {
        float x = acc[i] + bi;
        float mu = block_sum_256(x, sh) * (1.0f / NP);
        float d = x - mu;
        float var = block_sum_256(d * d, sh) * (1.0f / NP);
        float y = d * rsqrtf(var + 1e-5f) * ga + be;
        float nrm = sqrtf(block_sum_256(y * y, sh));
        y = y / fmaxf(nrm, 1e-12f);
        outp[(size_t)(a0 + i) * NP + p] = y;
    }
}

__global__ void gafd_kernel() {
    __shared__ float sh[33];
    float s = 0.f;
    const int total = NB * NA * NP;
    for (int i = blockIdx.x * blockDim.x + threadIdx.x; i < total;
         i += gridDim.x * blockDim.x) {
        float d = g_fs[i] - g_ft[i];
        s += d * d;
    }
    float bs = block_sum_256(s, sh);
    if (threadIdx.x == 0) atomicAdd(&g_gafd, bs);
}

__global__ void bd_kernel() {
    __shared__ float sh[33];
    int b = blockIdx.x;
    float s = g_sal[b * NA + threadIdx.x];
    float mx = block_max_256(s, sh);
    int bd = (s > 0.6f * mx) ? 1 : 0;
    g_bd[b * NA + threadIdx.x] = bd;
    float cnt = block_sum_256((float)bd, sh);
    if (threadIdx.x == 0) g_cnt[b] = (int)(cnt + 0.5f);
}

__global__ void abcd_kernel() {
    __shared__ float fsn[NP];
    __shared__ float sh[33];
    int blk = blockIdx.x;
    int b = blk >> 8, n = blk & 255;
    if (!g_bd[b * NA + n]) return;
    int t = threadIdx.x;
    float fv = g_fs[(size_t)(b * NA + n) * NP + t];
    float ftv = g_ft[(size_t)(b * NA + n) * NP + t];
    fsn[t] = fv;
    __syncthreads();
    float pos = block_sum_256(fv * ftv, sh) * 10.0f;  // /TAU
    const float4* fm = (const float4*)(g_fs + (size_t)(b * NA + t) * NP);
    float dm = 0.f;
#pragma unroll 4
    for (int q = 0; q < NP / 4; ++q) {
        float4 v = fm[q];
        dm += fsn[4 * q] * v.x + fsn[4 * q + 1] * v.y + fsn[4 * q + 2] * v.z +
              fsn[4 * q + 3] * v.w;
    }
    float val = g_bd[b * NA + t] ? -1e30f : dm * 10.0f;
    float mx = fmaxf(pos, block_max_256(val, sh));
    float e = (val < -1e29f) ? 0.f : expf(val - mx);
    float ssum = block_sum_256(e, sh) + expf(pos - mx);
    if (t == 0) atomicAdd(&g_abcd_b[b], mx + logf(ssum) - pos);
}

__global__ void final_kernel(float* __restrict__ out) {
    int t = threadIdx.x;
    float per = 0.f, valid = 0.f;
    if (t < NB) {
        int c = g_cnt[t];
        per = g_abcd_b[t] / fmaxf((float)c, 1.0f);
        valid = (c > 0 && c < NA) ? 1.0f : 0.0f;
    }
    float pv = per * valid;
#pragma unroll
    for (int o = 16; o; o >>= 1) {
        pv += __shfl_down_sync(0xffffffffu, pv, o);
        valid += __shfl_down_sync(0xffffffffu, valid, o);
    }
    if (t == 0) {
        float gafd = g_gafd * (1.0f / (NB * NA * NP));
        float abcd = (valid > 0.f) ? pv / valid : 0.f;
        out[0] = gafd + 0.5f * abcd;
        out[1] = gafd;
        out[2] = abcd;
    }
}

// ---------------- host launch ----------------
extern "C" void kernel_launch(void* const* d_in, const int* in_sizes, int n_in,
                              void* d_out, int out_size) {
    const float* T = (const float*)d_in[0];
    const float* Sf = (const float*)d_in[1];
    const float* w1 = (const float*)d_in[2];
    const float* b1 = (const float*)d_in[3];
    const float* w2 = (const float*)d_in[4];
    const float* b2 = (const float*)d_in[5];
    const float* tw = (const float*)d_in[6];
    const float* tb = (const float*)d_in[7];
    const float* tg = (const float*)d_in[8];
    const float* tbe = (const float*)d_in[9];
    const float* sw = (const float*)d_in[10];
    const float* sb = (const float*)d_in[11];
    const float* sg = (const float*)d_in[12];
    const float* sbe = (const float*)d_in[13];
    float* out = (float*)d_out;

    const int DSMEM = 2 * STAGE2;  // 81920 per CTA, 2 CTAs/SM
    static int s_attr_done = 0;
    if (!s_attr_done) {
        cudaFuncSetAttribute(convmma_kernel,
                             cudaFuncAttributeMaxDynamicSharedMemorySize, DSMEM);
        s_attr_done = 1;
    }

    reset_kernel<<<(NB * HW + 255) / 256, 256>>>();
    tprep_kernel<<<dim3(128, 32, 16), dim3(32, 8)>>>(T);
    wprep_kernel<<<(9 * CM * CT + 255) / 256, 256>>>(w1);
    convmma_kernel<<<dim3(4, 32, 16), 256, DSMEM>>>(b1, w2);
    softplus_kernel<<<NB * HW / 256, 256>>>(b2, out);
    score_kernel<<<16, 256>>>();
    topk_kernel<<<16, 512>>>();
    gather_kernel<<<NB * NA, 256>>>(T, Sf);
    proj_kernel<CT><<<512, 256>>>(tw, tb, tg, tbe);
    proj_kernel<CS><<<512, 256>>>(sw, sb, sg, sbe);
    gafd_kernel<<<256, 256>>>();
    bd_kernel<<<NB, 256>>>();
    abcd_kernel<<<NB * NA, 256>>>();
    final_kernel<<<1, 32>>>(out);
}

// round 11
// speedup vs baseline: 1.0689x; 1.0689x over previous
#include <cuda_runtime.h>
#include <cuda_bf16.h>
#include <math.h>
#include <stdint.h>

#define NB 16
#define CT 1024
#define CS 512
#define CM 512
#define HH 64
#define WW 64
#define HW 4096
#define NP 256
#define NA 256

// ---------------- scratch (device globals; no allocation) ----------------
__device__ float g_heatacc[NB * HW];  // conv+1x1 fused accumulator
__device__ float g_heat[NB * HW];
__device__ float g_score[NB * HW];
__device__ int   g_idx[NB * NA];
__device__ float g_sampT[NB * NA * CT];
__device__ float g_sampS[NB * NA * CS];
__device__ float g_sal[NB * NA];
__device__ float g_ft[NB * NA * NP];
__device__ float g_fs[NB * NA * NP];
__device__ int   g_bd[NB * NA];
__device__ int   g_cnt[NB];
__device__ float g_gafd;
__device__ float g_abcd_b[NB];

// bf16 hi/lo split tensors for tensor-core conv
__device__ __align__(16) __nv_bfloat16 g_Thi[NB * HW * CT];      // [b][p][ci]
__device__ __align__(16) __nv_bfloat16 g_Tlo[NB * HW * CT];
__device__ __align__(16) __nv_bfloat16 g_Whi[9 * CM * CT];       // [tap][co][ci]
__device__ __align__(16) __nv_bfloat16 g_Wlo[9 * CM * CT];

// ---------------- sm_80-class PTX helpers (compile on compute_103) --------
__device__ __forceinline__ uint32_t smem_to_u32(const void* smem_ptr) {
    uint32_t addr;
    asm("{ .reg .u64 tmp; cvta.to.shared.u64 tmp, %1; cvt.u32.u64 %0, tmp; }"
        : "=r"(addr) : "l"(smem_ptr));
    return addr;
}
__device__ __forceinline__ void cp16(uint32_t dst, const void* src, bool ok) {
    int sz = ok ? 16 : 0;
    asm volatile("cp.async.cg.shared.global [%0], [%1], 16, %2;"
                 :: "r"(dst), "l"(src), "r"(sz) : "memory");
}
#define CP_COMMIT() asm volatile("cp.async.commit_group;" ::: "memory")
#define CP_WAIT0()  asm volatile("cp.async.wait_group 0;" ::: "memory")

__device__ __forceinline__ void ldsm4(uint32_t* r, uint32_t addr) {
    asm volatile("ldmatrix.sync.aligned.m8n8.x4.shared.b16 {%0,%1,%2,%3}, [%4];"
                 : "=r"(r[0]), "=r"(r[1]), "=r"(r[2]), "=r"(r[3]) : "r"(addr));
}
__device__ __forceinline__ void mma16816(float* c, const uint32_t* a,
                                         uint32_t b0, uint32_t b1) {
    asm volatile(
        "mma.sync.aligned.m16n8k16.row.col.f32.bf16.bf16.f32 "
        "{%0,%1,%2,%3}, {%4,%5,%6,%7}, {%8,%9}, {%0,%1,%2,%3};"
        : "+f"(c[0]), "+f"(c[1]), "+f"(c[2]), "+f"(c[3])
        : "r"(a[0]), "r"(a[1]), "r"(a[2]), "r"(a[3]), "r"(b0), "r"(b1));
}

// ---------------- generic helpers ----------------
__device__ __forceinline__ float block_sum_256(float v, float* sh) {
#pragma unroll
    for (int o = 16; o; o >>= 1) v += __shfl_down_sync(0xffffffffu, v, o);
    __syncthreads();
    if ((threadIdx.x & 31) == 0) sh[threadIdx.x >> 5] = v;
    __syncthreads();
    if (threadIdx.x == 0) {
        float t = 0.f;
        for (int i = 0; i < 8; ++i) t += sh[i];
        sh[32] = t;
    }
    __syncthreads();
    return sh[32];
}

__device__ __forceinline__ float block_max_256(float v, float* sh) {
#pragma unroll
    for (int o = 16; o; o >>= 1) v = fmaxf(v, __shfl_down_sync(0xffffffffu, v, o));
    __syncthreads();
    if ((threadIdx.x & 31) == 0) sh[threadIdx.x >> 5] = v;
    __syncthreads();
    if (threadIdx.x == 0) {
        float t = sh[0];
        for (int i = 1; i < 8; ++i) t = fmaxf(t, sh[i]);
        sh[32] = t;
    }
    __syncthreads();
    return sh[32];
}

__device__ __forceinline__ void threefry2x32(unsigned k0, unsigned k1,
                                             unsigned x0, unsigned x1,
                                             unsigned& o0, unsigned& o1) {
    unsigned ks[3] = {k0, k1, k0 ^ k1 ^ 0x1BD11BDAu};
    x0 += ks[0];
    x1 += ks[1];
    const int R[5][4] = {{13, 15, 26, 6}, {17, 29, 16, 24}, {13, 15, 26, 6},
                         {17, 29, 16, 24}, {13, 15, 26, 6}};
#pragma unroll
    for (int g = 0; g < 5; ++g) {
#pragma unroll
        for (int q = 0; q < 4; ++q) {
            x0 += x1;
            int rr = R[g][q];
            x1 = (x1 << rr) | (x1 >> (32 - rr));
            x1 ^= x0;
        }
        x0 += ks[(g + 1) % 3];
        x1 += ks[(g + 2) % 3] + (unsigned)(g + 1);
    }
    o0 = x0;
    o1 = x1;
}

// ---------------- kernels ----------------
// zero heat accumulator + loss scalars (runs every launch; graph-safe)
__global__ void reset_kernel() {
    int i = blockIdx.x * blockDim.x + threadIdx.x;
    if (i < NB * HW) g_heatacc[i] = 0.f;
    if (i == 0) g_gafd = 0.f;
    if (i < NB) g_abcd_b[i] = 0.f;
}

// transpose + bf16 split of teacher feat: T[b][ci][p] -> Thi/Tlo[b][p][ci]
__global__ void tprep_kernel(const float* __restrict__ T) {
    __shared__ float tile[32][33];
    int b = blockIdx.z, p0 = blockIdx.x * 32, c0 = blockIdx.y * 32;
    int tx = threadIdx.x, ty = threadIdx.y;
    for (int i = ty; i < 32; i += 8)
        tile[i][tx] = T[((size_t)(b * CT + c0 + i)) * HW + p0 + tx];
    __syncthreads();
    for (int i = ty; i < 32; i += 8) {
        float v = tile[tx][i];
        __nv_bfloat16 h = __float2bfloat16(v);
        float hf = __bfloat162float(h);
        size_t o = ((size_t)b * HW + p0 + i) * CT + c0 + tx;
        g_Thi[o] = h;
        g_Tlo[o] = __float2bfloat16(v - hf);
    }
}

// weights split: W1[co][ci][tap] -> Whi/Wlo[tap][co][ci]
__global__ void wprep_kernel(const float* __restrict__ W1) {
    int idx = blockIdx.x * blockDim.x + threadIdx.x;
    if (idx >= 9 * CM * CT) return;
    int ci = idx & (CT - 1);
    int rest = idx >> 10;
    int co = rest & (CM - 1);
    int tap = rest >> 9;
    float w = W1[((size_t)co * CT + ci) * 9 + tap];
    __nv_bfloat16 h = __float2bfloat16(w);
    float hf = __bfloat162float(h);
    g_Whi[idx] = h;
    g_Wlo[idx] = __float2bfloat16(w - hf);
}

// conv1 (bf16x3 implicit GEMM via mma.sync) fused with the 1x1 conv.
// CTA: 512 threads, 128 px x 256 co. 2-stage cp.async pipeline with
// CUTLASS-style single __syncthreads per K-chunk (K=64), loads fully
// overlapped with compute.
#define ROWB 144                      // bytes per smem row (64 bf16 + 8 pad)
#define A_BYTES (128 * ROWB)          // 18432
#define B_BYTES (256 * ROWB)          // 36864
#define STAGE_BYTES (2 * A_BYTES + 2 * B_BYTES)  // 110592
__global__ __launch_bounds__(512, 1)
void convmma_kernel(const float* __restrict__ b1, const float* __restrict__ w2) {
    extern __shared__ char dsm[];
    uint32_t sb = smem_to_u32(dsm);
    int tid = threadIdx.x, lane = tid & 31, wid = tid >> 5;
    int co0 = blockIdx.x * 256;
    int pixtile = blockIdx.y;
    int bb = blockIdx.z;
    int y0 = pixtile * 2, p0 = pixtile * 128;
    int wm = wid & 3, wn = wid >> 2;   // 4 M-groups of 32 px; 4 N-groups of 64 co

    float acc[2][8][4];
#pragma unroll
    for (int i = 0; i < 2; ++i)
#pragma unroll
        for (int j = 0; j < 8; ++j)
#pragma unroll
            for (int k = 0; k < 4; ++k) acc[i][j][k] = 0.f;

    auto load_chunk = [&](int c, int s) {
        int tap = c >> 4, kc = c & 15;
        int dy = tap / 3 - 1, dx = tap % 3 - 1;
        int ci0 = kc * 64;
        uint32_t base = sb + (uint32_t)s * STAGE_BYTES;
        // A: 128 pixel rows x 64 ci, shifted + zero-masked (hi @0, lo @A_BYTES)
#pragma unroll
        for (int i = 0; i < 2; ++i) {
            int u = i * 512 + tid;
            int r = u >> 3, seg = u & 7;
            int ys = y0 + (r >> 6) + dy;
            int xs = (r & 63) + dx;
            bool ok = ((unsigned)ys < 64u) && ((unsigned)xs < 64u);
            int ysc = ok ? ys : 0, xsc = ok ? xs : 0;
            size_t g = ((size_t)(bb * HW + ysc * 64 + xsc)) * CT + ci0 + seg * 8;
            uint32_t off = (uint32_t)(r * ROWB + seg * 16);
            cp16(base + off, g_Thi + g, ok);
            cp16(base + A_BYTES + off, g_Tlo + g, ok);
        }
        // B: 256 co rows x 64 ci (hi @2*A_BYTES, lo @2*A_BYTES+B_BYTES)
#pragma unroll
        for (int i = 0; i < 4; ++i) {
            int u = i * 512 + tid;
            int r = u >> 3, seg = u & 7;
            size_t g = ((size_t)(tap * CM + co0 + r)) * CT + ci0 + seg * 8;
            uint32_t off = (uint32_t)(r * ROWB + seg * 16);
            cp16(base + 2 * A_BYTES + off, g_Whi + g, true);
            cp16(base + 2 * A_BYTES + B_BYTES + off, g_Wlo + g, true);
        }
    };

    auto compute = [&](int s) {
        uint32_t Ah = sb + (uint32_t)s * STAGE_BYTES;
        uint32_t Al = Ah + A_BYTES;
        uint32_t Bh = Ah + 2 * A_BYTES;
        uint32_t Bl = Bh + B_BYTES;
#pragma unroll
        for (int ks = 0; ks < 4; ++ks) {
            uint32_t aH[2][4], aL[2][4];
#pragma unroll
            for (int t = 0; t < 2; ++t) {
                uint32_t ra = (uint32_t)((wm * 32 + t * 16 + (lane & 15)) * ROWB +
                                         ks * 32 + (lane >> 4) * 16);
                ldsm4(aH[t], Ah + ra);
                ldsm4(aL[t], Al + ra);
            }
#pragma unroll
            for (int nt = 0; nt < 4; ++nt) {
                uint32_t rb = (uint32_t)((wn * 64 + nt * 16 + (lane & 15)) * ROWB +
                                         ks * 32 + (lane >> 4) * 16);
                uint32_t bHf[4], bLf[4];
                ldsm4(bHf, Bh + rb);
                ldsm4(bLf, Bl + rb);
#pragma unroll
                for (int mi = 0; mi < 2; ++mi) {
                    mma16816(acc[mi][2 * nt], aH[mi], bHf[0], bHf[2]);
                    mma16816(acc[mi][2 * nt + 1], aH[mi], bHf[1], bHf[3]);
                    mma16816(acc[mi][2 * nt], aL[mi], bHf[0], bHf[2]);
                    mma16816(acc[mi][2 * nt + 1], aL[mi], bHf[1], bHf[3]);
                    mma16816(acc[mi][2 * nt], aH[mi], bLf[0], bLf[2]);
                    mma16816(acc[mi][2 * nt + 1], aH[mi], bLf[1], bLf[3]);
                }
            }
        }
    };

    // prologue: stage 0 in flight
    load_chunk(0, 0);
    CP_COMMIT();
#pragma unroll 1
    for (int c = 0; c < 144; ++c) {
        int s = c & 1;
        CP_WAIT0();          // stage c's loads (issued last iteration) done
        __syncthreads();     // visibility + proves compute(c-1) done -> s^1 free
        if (c + 1 < 144) {
            load_chunk(c + 1, s ^ 1);   // overlaps with compute(c)
            CP_COMMIT();
        }
        compute(c & 1 ? 1 : 0);
    }

    // fused epilogue: h = relu(acc + b1); heatacc[p] += sum_co h * w2[co]
    float hp[2][2] = {{0.f, 0.f}, {0.f, 0.f}};  // [mi][row-half]
#pragma unroll
    for (int mi = 0; mi < 2; ++mi) {
#pragma unroll
        for (int nt = 0; nt < 8; ++nt) {
            int co = co0 + wn * 64 + nt * 8 + (lane & 3) * 2;
            float bv0 = b1[co], bv1 = b1[co + 1];
            float w20 = w2[co], w21 = w2[co + 1];
            float h00 = fmaxf(acc[mi][nt][0] + bv0, 0.f);
            float h01 = fmaxf(acc[mi][nt][1] + bv1, 0.f);
            float h10 = fmaxf(acc[mi][nt][2] + bv0, 0.f);
            float h11 = fmaxf(acc[mi][nt][3] + bv1, 0.f);
            hp[mi][0] += h00 * w20 + h01 * w21;
            hp[mi][1] += h10 * w20 + h11 * w21;
        }
    }
#pragma unroll
    for (int mi = 0; mi < 2; ++mi) {
        int r0 = wm * 32 + mi * 16 + (lane >> 2);
        atomicAdd(&g_heatacc[bb * HW + p0 + r0], hp[mi][0]);
        atomicAdd(&g_heatacc[bb * HW + p0 + r0 + 8], hp[mi][1]);
    }
}

// softplus(acc + b2) -> heatmap (scratch + output)
__global__ void softplus_kernel(const float* __restrict__ b2,
                                float* __restrict__ out) {
    int i = blockIdx.x * 256 + threadIdx.x;
    float a = g_heatacc[i] + b2[0];
    float sp = fmaxf(a, 0.f) + log1pf(expf(-fabsf(a)));
    g_heat[i] = sp;
    out[3 + i] = sp;
}

// per-batch: normalize to prob, add JAX (partitionable threefry) Gumbel -> score
__global__ void score_kernel() {
    __shared__ float sh[33];
    int b = blockIdx.x;
    float s = 0.f;
    for (int p = threadIdx.x; p < HW; p += 256) s += g_heat[b * HW + p];
    float S = block_sum_256(s, sh);
    for (int p = threadIdx.x; p < HW; p += 256) {
        unsigned gi = (unsigned)(b * HW + p);
        unsigned o0, o1;
        threefry2x32(0u, 42u, 0u, gi, o0, o1);
        unsigned bits = o0 ^ o1;
        float f = __uint_as_float((bits >> 9) | 0x3f800000u) - 1.0f;
        float u = fmaxf(1e-8f, f * (1.0f - 1e-8f) + 1e-8f);
        float gum = -logf(-logf(u));
        g_score[gi] = logf(g_heat[gi] / (S + 1e-6f) + 1e-12f) + gum;
    }
}

// top-256 per batch via in-smem bitonic sort
__global__ void topk_kernel() {
    __shared__ float key[HW];
    __shared__ int val[HW];
    int b = blockIdx.x;
    for (int i = threadIdx.x; i < HW; i += blockDim.x) {
        key[i] = -g_score[b * HW + i];
        val[i] = i;
    }
    for (int k = 2; k <= HW; k <<= 1)
        for (int j = k >> 1; j > 0; j >>= 1) {
            __syncthreads();
            for (int i = threadIdx.x; i < HW; i += blockDim.x) {
                int p = i ^ j;
                if (p > i) {
                    bool up = ((i & k) == 0);
                    float ki = key[i], kp = key[p];
                    if ((ki > kp) == up) {
                        key[i] = kp;
                        key[p] = ki;
                        int t = val[i];
                        val[i] = val[p];
                        val[p] = t;
                    }
                }
            }
        }
    __syncthreads();
    for (int i = threadIdx.x; i < NA; i += blockDim.x) g_idx[b * NA + i] = val[i];
}

// bilinear sample == 0.25 * sum of 4 pixels with zero pad
__global__ void gather_kernel(const float* __restrict__ T,
                              const float* __restrict__ Sf) {
    int blk = blockIdx.x;
    int b = blk >> 8, n = blk & 255;
    int idx = g_idx[b * NA + n];
    int r = idx >> 6, c = idx & 63;
    bool rv = r > 0, cv = c > 0;
    int o11 = r * WW + c, o10 = o11 - 1, o01 = o11 - WW, o00 = o01 - 1;
    for (int ch = threadIdx.x; ch < CT; ch += blockDim.x) {
        const float* base = T + (size_t)(b * CT + ch) * HW;
        float s = base[o11];
        if (cv) s += base[o10];
        if (rv) {
            s += base[o01];
            if (cv) s += base[o00];
        }
        g_sampT[(size_t)(b * NA + n) * CT + ch] = 0.25f * s;
    }
    for (int ch = threadIdx.x; ch < CS; ch += blockDim.x) {
        const float* base = Sf + (size_t)(b * CS + ch) * HW;
        float s = base[o11];
        if (cv) s += base[o10];
        if (rv) {
            s += base[o01];
            if (cv) s += base[o00];
        }
        g_sampS[(size_t)(b * NA + n) * CS + ch] = 0.25f * s;
    }
    if (threadIdx.x == 0) {
        const float* base = g_heat + b * HW;
        float s = base[o11];
        if (cv) s += base[o10];
        if (rv) {
            s += base[o01];
            if (cv) s += base[o00];
        }
        g_sal[b * NA + n] = 0.25f * s;
    }
}

// [rows,C]@[C,256] + bias -> LayerNorm -> l2norm. 8 rows per block, thread = p.
template <int C>
__global__ void proj_kernel(const float* __restrict__ wmat,
                            const float* __restrict__ bias,
                            const float* __restrict__ gamma,
                            const float* __restrict__ beta) {
    __shared__ float sRow[8 * C];
    __shared__ float sh[33];
    const float* samp = (C == CT) ? g_sampT : g_sampS;
    float* outp = (C == CT) ? g_ft : g_fs;
    int a0 = blockIdx.x * 8;
    int p = threadIdx.x;
    for (int i = threadIdx.x; i < 8 * C; i += 256) sRow[i] = samp[(size_t)a0 * C + i];
    __syncthreads();
    float acc[8];
#pragma unroll
    for (int i = 0; i < 8; ++i) acc[i] = 0.f;
    for (int c = 0; c < C; ++c) {
        float w = wmat[(size_t)c * NP + p];
#pragma unroll
        for (int i = 0; i < 8; ++i) acc[i] += sRow[i * C + c] * w;
    }
    float bi = bias[p], ga = gamma[p], be = beta[p];
#pragma unroll 1
    for (int i = 0; i < 8; ++i) {
        float x = acc[i] + bi;
        float mu = block_sum_256(x, sh) * (1.0f / NP);
        float d = x - mu;
        float var = block_sum_256(d * d, sh) * (1.0f / NP);
        float y = d * rsqrtf(var + 1e-5f) * ga + be;
        float nrm = sqrtf(block_sum_256(y * y, sh));
        y = y / fmaxf(nrm, 1e-12f);
        outp[(size_t)(a0 + i) * NP + p] = y;
    }
}

__global__ void gafd_kernel() {
    __shared__ float sh[33];
    float s = 0.f;
    const int total = NB * NA * NP;
    for (int i = blockIdx.x * blockDim.x + threadIdx.x; i < total;
         i += gridDim.x * blockDim.x) {
        float d = g_fs[i] - g_ft[i];
        s += d * d;
    }
    float bs = block_sum_256(s, sh);
    if (threadIdx.x == 0) atomicAdd(&g_gafd, bs);
}

__global__ void bd_kernel() {
    __shared__ float sh[33];
    int b = blockIdx.x;
    float s = g_sal[b * NA + threadIdx.x];
    float mx = block_max_256(s, sh);
    int bd = (s > 0.6f * mx) ? 1 : 0;
    g_bd[b * NA + threadIdx.x] = bd;
    float cnt = block_sum_256((float)bd, sh);
    if (threadIdx.x == 0) g_cnt[b] = (int)(cnt + 0.5f);
}

__global__ void abcd_kernel() {
    __shared__ float fsn[NP];
    __shared__ float sh[33];
    int blk = blockIdx.x;
    int b = blk >> 8, n = blk & 255;
    if (!g_bd[b * NA + n]) return;
    int t = threadIdx.x;
    float fv = g_fs[(size_t)(b * NA + n) * NP + t];
    float ftv = g_ft[(size_t)(b * NA + n) * NP + t];
    fsn[t] = fv;
    __syncthreads();
    float pos = block_sum_256(fv * ftv, sh) * 10.0f;  // /TAU
    const float4* fm = (const float4*)(g_fs + (size_t)(b * NA + t) * NP);
    float dm = 0.f;
#pragma unroll 4
    for (int q = 0; q < NP / 4; ++q) {
        float4 v = fm[q];
        dm += fsn[4 * q] * v.x + fsn[4 * q + 1] * v.y + fsn[4 * q + 2] * v.z +
              fsn[4 * q + 3] * v.w;
    }
    float val = g_bd[b * NA + t] ? -1e30f : dm * 10.0f;
    float mx = fmaxf(pos, block_max_256(val, sh));
    float e = (val < -1e29f) ? 0.f : expf(val - mx);
    float ssum = block_sum_256(e, sh) + expf(pos - mx);
    if (t == 0) atomicAdd(&g_abcd_b[b], mx + logf(ssum) - pos);
}

__global__ void final_kernel(float* __restrict__ out) {
    int t = threadIdx.x;
    float per = 0.f, valid = 0.f;
    if (t < NB) {
        int c = g_cnt[t];
        per = g_abcd_b[t] / fmaxf((float)c, 1.0f);
        valid = (c > 0 && c < NA) ? 1.0f : 0.0f;
    }
    float pv = per * valid;
#pragma unroll
    for (int o = 16; o; o >>= 1) {
        pv += __shfl_down_sync(0xffffffffu, pv, o);
        valid += __shfl_down_sync(0xffffffffu, valid, o);
    }
    if (t == 0) {
        float gafd = g_gafd * (1.0f / (NB * NA * NP));
        float abcd = (valid > 0.f) ? pv / valid : 0.f;
        out[0] = gafd + 0.5f * abcd;
        out[1] = gafd;
        out[2] = abcd;
    }
}

// ---------------- host launch ----------------
extern "C" void kernel_launch(void* const* d_in, const int* in_sizes, int n_in,
                              void* d_out, int out_size) {
    const float* T = (const float*)d_in[0];
    const float* Sf = (const float*)d_in[1];
    const float* w1 = (const float*)d_in[2];
    const float* b1 = (const float*)d_in[3];
    const float* w2 = (const float*)d_in[4];
    const float* b2 = (const float*)d_in[5];
    const float* tw = (const float*)d_in[6];
    const float* tb = (const float*)d_in[7];
    const float* tg = (const float*)d_in[8];
    const float* tbe = (const float*)d_in[9];
    const float* sw = (const float*)d_in[10];
    const float* sb = (const float*)d_in[11];
    const float* sg = (const float*)d_in[12];
    const float* sbe = (const float*)d_in[13];
    float* out = (float*)d_out;

    const int DSMEM = 2 * STAGE_BYTES;  // 221184
    static int s_attr_done = 0;
    if (!s_attr_done) {
        cudaFuncSetAttribute(convmma_kernel,
                             cudaFuncAttributeMaxDynamicSharedMemorySize, DSMEM);
        s_attr_done = 1;
    }

    reset_kernel<<<(NB * HW + 255) / 256, 256>>>();
    tprep_kernel<<<dim3(128, 32, 16), dim3(32, 8)>>>(T);
    wprep_kernel<<<(9 * CM * CT + 255) / 256, 256>>>(w1);
    convmma_kernel<<<dim3(2, 32, 16), 512, DSMEM>>>(b1, w2);
    softplus_kernel<<<NB * HW / 256, 256>>>(b2, out);
    score_kernel<<<16, 256>>>();
    topk_kernel<<<16, 512>>>();
    gather_kernel<<<NB * NA, 256>>>(T, Sf);
    proj_kernel<CT><<<512, 256>>>(tw, tb, tg, tbe);
    proj_kernel<CS><<<512, 256>>>(sw, sb, sg, sbe);
    gafd_kernel<<<256, 256>>>();
    bd_kernel<<<NB, 256>>>();
    abcd_kernel<<<NB * NA, 256>>>();
    final_kernel<<<1, 32>>>(out);
}

// round 12
// speedup vs baseline: 1.1077x; 1.0363x over previous
#include <cuda_runtime.h>
#include <cuda_bf16.h>
#include <math.h>
#include <stdint.h>

#define NB 16
#define CT 1024
#define CS 512
#define CM 512
#define HH 64
#define WW 64
#define HW 4096
#define NP 256
#define NA 256

// ---------------- scratch (device globals; no allocation) ----------------
__device__ float g_heatacc[NB * HW];  // conv+1x1 fused accumulator
__device__ float g_heat[NB * HW];
__device__ float g_score[NB * HW];
__device__ int   g_idx[NB * NA];
__device__ float g_sampT[NB * NA * CT];
__device__ float g_sampS[NB * NA * CS];
__device__ float g_sal[NB * NA];
__device__ float g_ft[NB * NA * NP];
__device__ float g_fs[NB * NA * NP];
__device__ int   g_bd[NB * NA];
__device__ int   g_cnt[NB];
__device__ float g_gafd;
__device__ float g_abcd_b[NB];

// bf16 hi/lo split tensors for tensor-core conv
__device__ __align__(16) __nv_bfloat16 g_Thi[NB * HW * CT];      // [b][p][ci]
__device__ __align__(16) __nv_bfloat16 g_Tlo[NB * HW * CT];
__device__ __align__(16) __nv_bfloat16 g_Whi[9 * CM * CT];       // [tap][co][ci]
__device__ __align__(16) __nv_bfloat16 g_Wlo[9 * CM * CT];

// ---------------- sm_80-class PTX helpers (compile on compute_103) --------
__device__ __forceinline__ uint32_t smem_to_u32(const void* smem_ptr) {
    uint32_t addr;
    asm("{ .reg .u64 tmp; cvta.to.shared.u64 tmp, %1; cvt.u32.u64 %0, tmp; }"
        : "=r"(addr) : "l"(smem_ptr));
    return addr;
}
__device__ __forceinline__ void cp16(uint32_t dst, const void* src, bool ok) {
    int sz = ok ? 16 : 0;
    asm volatile("cp.async.cg.shared.global [%0], [%1], 16, %2;"
                 :: "r"(dst), "l"(src), "r"(sz) : "memory");
}
#define CP_COMMIT() asm volatile("cp.async.commit_group;" ::: "memory")
#define CP_WAIT0()  asm volatile("cp.async.wait_group 0;" ::: "memory")

__device__ __forceinline__ void ldsm4(uint32_t* r, uint32_t addr) {
    asm volatile("ldmatrix.sync.aligned.m8n8.x4.shared.b16 {%0,%1,%2,%3}, [%4];"
                 : "=r"(r[0]), "=r"(r[1]), "=r"(r[2]), "=r"(r[3]) : "r"(addr));
}
__device__ __forceinline__ void mma16816(float* c, const uint32_t* a,
                                         uint32_t b0, uint32_t b1) {
    asm volatile(
        "mma.sync.aligned.m16n8k16.row.col.f32.bf16.bf16.f32 "
        "{%0,%1,%2,%3}, {%4,%5,%6,%7}, {%8,%9}, {%0,%1,%2,%3};"
        : "+f"(c[0]), "+f"(c[1]), "+f"(c[2]), "+f"(c[3])
        : "r"(a[0]), "r"(a[1]), "r"(a[2]), "r"(a[3]), "r"(b0), "r"(b1));
}

// ---------------- generic helpers ----------------
__device__ __forceinline__ float block_sum_256(float v, float* sh) {
#pragma unroll
    for (int o = 16; o; o >>= 1) v += __shfl_down_sync(0xffffffffu, v, o);
    __syncthreads();
    if ((threadIdx.x & 31) == 0) sh[threadIdx.x >> 5] = v;
    __syncthreads();
    if (threadIdx.x == 0) {
        float t = 0.f;
        for (int i = 0; i < 8; ++i) t += sh[i];
        sh[32] = t;
    }
    __syncthreads();
    return sh[32];
}

__device__ __forceinline__ float block_max_256(float v, float* sh) {
#pragma unroll
    for (int o = 16; o; o >>= 1) v = fmaxf(v, __shfl_down_sync(0xffffffffu, v, o));
    __syncthreads();
    if ((threadIdx.x & 31) == 0) sh[threadIdx.x >> 5] = v;
    __syncthreads();
    if (threadIdx.x == 0) {
        float t = sh[0];
        for (int i = 1; i < 8; ++i) t = fmaxf(t, sh[i]);
        sh[32] = t;
    }
    __syncthreads();
    return sh[32];
}

__device__ __forceinline__ void threefry2x32(unsigned k0, unsigned k1,
                                             unsigned x0, unsigned x1,
                                             unsigned& o0, unsigned& o1) {
    unsigned ks[3] = {k0, k1, k0 ^ k1 ^ 0x1BD11BDAu};
    x0 += ks[0];
    x1 += ks[1];
    const int R[5][4] = {{13, 15, 26, 6}, {17, 29, 16, 24}, {13, 15, 26, 6},
                         {17, 29, 16, 24}, {13, 15, 26, 6}};
#pragma unroll
    for (int g = 0; g < 5; ++g) {
#pragma unroll
        for (int q = 0; q < 4; ++q) {
            x0 += x1;
            int rr = R[g][q];
            x1 = (x1 << rr) | (x1 >> (32 - rr));
            x1 ^= x0;
        }
        x0 += ks[(g + 1) % 3];
        x1 += ks[(g + 2) % 3] + (unsigned)(g + 1);
    }
    o0 = x0;
    o1 = x1;
}

// ---------------- kernels ----------------
// zero heat accumulator + loss scalars (runs every launch; graph-safe)
__global__ void reset_kernel() {
    int i = blockIdx.x * blockDim.x + threadIdx.x;
    if (i < NB * HW) g_heatacc[i] = 0.f;
    if (i == 0) g_gafd = 0.f;
    if (i < NB) g_abcd_b[i] = 0.f;
}

// transpose + bf16 split of teacher feat: T[b][ci][p] -> Thi/Tlo[b][p][ci]
__global__ void tprep_kernel(const float* __restrict__ T) {
    __shared__ float tile[32][33];
    int b = blockIdx.z, p0 = blockIdx.x * 32, c0 = blockIdx.y * 32;
    int tx = threadIdx.x, ty = threadIdx.y;
    for (int i = ty; i < 32; i += 8)
        tile[i][tx] = T[((size_t)(b * CT + c0 + i)) * HW + p0 + tx];
    __syncthreads();
    for (int i = ty; i < 32; i += 8) {
        float v = tile[tx][i];
        __nv_bfloat16 h = __float2bfloat16(v);
        float hf = __bfloat162float(h);
        size_t o = ((size_t)b * HW + p0 + i) * CT + c0 + tx;
        g_Thi[o] = h;
        g_Tlo[o] = __float2bfloat16(v - hf);
    }
}

// weights split: W1[co][ci][tap] -> Whi/Wlo[tap][co][ci]
__global__ void wprep_kernel(const float* __restrict__ W1) {
    int idx = blockIdx.x * blockDim.x + threadIdx.x;
    if (idx >= 9 * CM * CT) return;
    int ci = idx & (CT - 1);
    int rest = idx >> 10;
    int co = rest & (CM - 1);
    int tap = rest >> 9;
    float w = W1[((size_t)co * CT + ci) * 9 + tap];
    __nv_bfloat16 h = __float2bfloat16(w);
    float hf = __bfloat162float(h);
    g_Whi[idx] = h;
    g_Wlo[idx] = __float2bfloat16(w - hf);
}

// conv1 (bf16x3 implicit GEMM via mma.sync) fused with the 1x1 conv.
// CTA: 512 threads, 128 px x 256 co. 2-stage cp.async pipeline, single
// __syncthreads per K-chunk, PASS-MAJOR MMA ordering (acc reuse distance 16).
#define ROWB 144                      // bytes per smem row (64 bf16 + 8 pad)
#define A_BYTES (128 * ROWB)          // 18432
#define B_BYTES (256 * ROWB)          // 36864
#define STAGE_BYTES (2 * A_BYTES + 2 * B_BYTES)  // 110592
__global__ __launch_bounds__(512, 1)
void convmma_kernel(const float* __restrict__ b1, const float* __restrict__ w2) {
    extern __shared__ char dsm[];
    uint32_t sb = smem_to_u32(dsm);
    int tid = threadIdx.x, lane = tid & 31, wid = tid >> 5;
    int co0 = blockIdx.x * 256;
    int pixtile = blockIdx.y;
    int bb = blockIdx.z;
    int y0 = pixtile * 2, p0 = pixtile * 128;
    int wm = wid & 3, wn = wid >> 2;   // 4 M-groups of 32 px; 4 N-groups of 64 co

    float acc[2][8][4];
#pragma unroll
    for (int i = 0; i < 2; ++i)
#pragma unroll
        for (int j = 0; j < 8; ++j)
#pragma unroll
            for (int k = 0; k < 4; ++k) acc[i][j][k] = 0.f;

    auto load_chunk = [&](int c, int s) {
        int tap = c >> 4, kc = c & 15;
        int dy = tap / 3 - 1, dx = tap % 3 - 1;
        int ci0 = kc * 64;
        uint32_t base = sb + (uint32_t)s * STAGE_BYTES;
        // A: 128 pixel rows x 64 ci, shifted + zero-masked (hi @0, lo @A_BYTES)
#pragma unroll
        for (int i = 0; i < 2; ++i) {
            int u = i * 512 + tid;
            int r = u >> 3, seg = u & 7;
            int ys = y0 + (r >> 6) + dy;
            int xs = (r & 63) + dx;
            bool ok = ((unsigned)ys < 64u) && ((unsigned)xs < 64u);
            int ysc = ok ? ys : 0, xsc = ok ? xs : 0;
            size_t g = ((size_t)(bb * HW + ysc * 64 + xsc)) * CT + ci0 + seg * 8;
            uint32_t off = (uint32_t)(r * ROWB + seg * 16);
            cp16(base + off, g_Thi + g, ok);
            cp16(base + A_BYTES + off, g_Tlo + g, ok);
        }
        // B: 256 co rows x 64 ci (hi @2*A_BYTES, lo @2*A_BYTES+B_BYTES)
#pragma unroll
        for (int i = 0; i < 4; ++i) {
            int u = i * 512 + tid;
            int r = u >> 3, seg = u & 7;
            size_t g = ((size_t)(tap * CM + co0 + r)) * CT + ci0 + seg * 8;
            uint32_t off = (uint32_t)(r * ROWB + seg * 16);
            cp16(base + 2 * A_BYTES + off, g_Whi + g, true);
            cp16(base + 2 * A_BYTES + B_BYTES + off, g_Wlo + g, true);
        }
    };

    auto compute = [&](int s) {
        uint32_t Ah = sb + (uint32_t)s * STAGE_BYTES;
        uint32_t Al = Ah + A_BYTES;
        uint32_t Bh = Ah + 2 * A_BYTES;
        uint32_t Bl = Bh + B_BYTES;
#pragma unroll
        for (int ks = 0; ks < 4; ++ks) {
            uint32_t aH[2][4], aL[2][4], bH[4][4], bL[4][4];
#pragma unroll
            for (int t = 0; t < 2; ++t) {
                uint32_t ra = (uint32_t)((wm * 32 + t * 16 + (lane & 15)) * ROWB +
                                         ks * 32 + (lane >> 4) * 16);
                ldsm4(aH[t], Ah + ra);
                ldsm4(aL[t], Al + ra);
            }
#pragma unroll
            for (int nt = 0; nt < 4; ++nt) {
                uint32_t rb = (uint32_t)((wn * 64 + nt * 16 + (lane & 15)) * ROWB +
                                         ks * 32 + (lane >> 4) * 16);
                ldsm4(bH[nt], Bh + rb);
                ldsm4(bL[nt], Bl + rb);
            }
            // pass-major: each accumulator is revisited only after 16 MMAs
            // pass 0: Ahi x Bhi
#pragma unroll
            for (int nt = 0; nt < 4; ++nt)
#pragma unroll
                for (int mi = 0; mi < 2; ++mi) {
                    mma16816(acc[mi][2 * nt], aH[mi], bH[nt][0], bH[nt][2]);
                    mma16816(acc[mi][2 * nt + 1], aH[mi], bH[nt][1], bH[nt][3]);
                }
            // pass 1: Alo x Bhi
#pragma unroll
            for (int nt = 0; nt < 4; ++nt)
#pragma unroll
                for (int mi = 0; mi < 2; ++mi) {
                    mma16816(acc[mi][2 * nt], aL[mi], bH[nt][0], bH[nt][2]);
                    mma16816(acc[mi][2 * nt + 1], aL[mi], bH[nt][1], bH[nt][3]);
                }
            // pass 2: Ahi x Blo
#pragma unroll
            for (int nt = 0; nt < 4; ++nt)
#pragma unroll
                for (int mi = 0; mi < 2; ++mi) {
                    mma16816(acc[mi][2 * nt], aH[mi], bL[nt][0], bL[nt][2]);
                    mma16816(acc[mi][2 * nt + 1], aH[mi], bL[nt][1], bL[nt][3]);
                }
        }
    };

    // prologue: stage 0 in flight
    load_chunk(0, 0);
    CP_COMMIT();
#pragma unroll 1
    for (int c = 0; c < 144; ++c) {
        int s = c & 1;
        CP_WAIT0();          // stage c's loads (issued last iteration) done
        __syncthreads();     // visibility + proves compute(c-1) done -> s^1 free
        if (c + 1 < 144) {
            load_chunk(c + 1, s ^ 1);   // overlaps with compute(c)
            CP_COMMIT();
        }
        compute(s);
    }

    // fused epilogue: h = relu(acc + b1); heatacc[p] += sum_co h * w2[co]
    float hp[2][2] = {{0.f, 0.f}, {0.f, 0.f}};  // [mi][row-half]
#pragma unroll
    for (int mi = 0; mi < 2; ++mi) {
#pragma unroll
        for (int nt = 0; nt < 8; ++nt) {
            int co = co0 + wn * 64 + nt * 8 + (lane & 3) * 2;
            float bv0 = b1[co], bv1 = b1[co + 1];
            float w20 = w2[co], w21 = w2[co + 1];
            float h00 = fmaxf(acc[mi][nt][0] + bv0, 0.f);
            float h01 = fmaxf(acc[mi][nt][1] + bv1, 0.f);
            float h10 = fmaxf(acc[mi][nt][2] + bv0, 0.f);
            float h11 = fmaxf(acc[mi][nt][3] + bv1, 0.f);
            hp[mi][0] += h00 * w20 + h01 * w21;
            hp[mi][1] += h10 * w20 + h11 * w21;
        }
    }
#pragma unroll
    for (int mi = 0; mi < 2; ++mi) {
        int r0 = wm * 32 + mi * 16 + (lane >> 2);
        atomicAdd(&g_heatacc[bb * HW + p0 + r0], hp[mi][0]);
        atomicAdd(&g_heatacc[bb * HW + p0 + r0 + 8], hp[mi][1]);
    }
}

// softplus(acc + b2) -> heatmap (scratch + output)
__global__ void softplus_kernel(const float* __restrict__ b2,
                                float* __restrict__ out) {
    int i = blockIdx.x * 256 + threadIdx.x;
    float a = g_heatacc[i] + b2[0];
    float sp = fmaxf(a, 0.f) + log1pf(expf(-fabsf(a)));
    g_heat[i] = sp;
    out[3 + i] = sp;
}

// per-batch: normalize to prob, add JAX (partitionable threefry) Gumbel -> score
__global__ void score_kernel() {
    __shared__ float sh[33];
    int b = blockIdx.x;
    float s = 0.f;
    for (int p = threadIdx.x; p < HW; p += 256) s += g_heat[b * HW + p];
    float S = block_sum_256(s, sh);
    for (int p = threadIdx.x; p < HW; p += 256) {
        unsigned gi = (unsigned)(b * HW + p);
        unsigned o0, o1;
        threefry2x32(0u, 42u, 0u, gi, o0, o1);
        unsigned bits = o0 ^ o1;
        float f = __uint_as_float((bits >> 9) | 0x3f800000u) - 1.0f;
        float u = fmaxf(1e-8f, f * (1.0f - 1e-8f) + 1e-8f);
        float gum = -logf(-logf(u));
        g_score[gi] = logf(g_heat[gi] / (S + 1e-6f) + 1e-12f) + gum;
    }
}

// top-256 per batch via in-smem bitonic sort
__global__ void topk_kernel() {
    __shared__ float key[HW];
    __shared__ int val[HW];
    int b = blockIdx.x;
    for (int i = threadIdx.x; i < HW; i += blockDim.x) {
        key[i] = -g_score[b * HW + i];
        val[i] = i;
    }
    for (int k = 2; k <= HW; k <<= 1)
        for (int j = k >> 1; j > 0; j >>= 1) {
            __syncthreads();
            for (int i = threadIdx.x; i < HW; i += blockDim.x) {
                int p = i ^ j;
                if (p > i) {
                    bool up = ((i & k) == 0);
                    float ki = key[i], kp = key[p];
                    if ((ki > kp) == up) {
                        key[i] = kp;
                        key[p] = ki;
                        int t = val[i];
                        val[i] = val[p];
                        val[p] = t;
                    }
                }
            }
        }
    __syncthreads();
    for (int i = threadIdx.x; i < NA; i += blockDim.x) g_idx[b * NA + i] = val[i];
}

// bilinear sample == 0.25 * sum of 4 pixels with zero pad
__global__ void gather_kernel(const float* __restrict__ T,
                              const float* __restrict__ Sf) {
    int blk = blockIdx.x;
    int b = blk >> 8, n = blk & 255;
    int idx = g_idx[b * NA + n];
    int r = idx >> 6, c = idx & 63;
    bool rv = r > 0, cv = c > 0;
    int o11 = r * WW + c, o10 = o11 - 1, o01 = o11 - WW, o00 = o01 - 1;
    for (int ch = threadIdx.x; ch < CT; ch += blockDim.x) {
        const float* base = T + (size_t)(b * CT + ch) * HW;
        float s = base[o11];
        if (cv) s += base[o10];
        if (rv) {
            s += base[o01];
            if (cv) s += base[o00];
        }
        g_sampT[(size_t)(b * NA + n) * CT + ch] = 0.25f * s;
    }
    for (int ch = threadIdx.x; ch < CS; ch += blockDim.x) {
        const float* base = Sf + (size_t)(b * CS + ch) * HW;
        float s = base[o11];
        if (cv) s += base[o10];
        if (rv) {
            s += base[o01];
            if (cv) s += base[o00];
        }
        g_sampS[(size_t)(b * NA + n) * CS + ch] = 0.25f * s;
    }
    if (threadIdx.x == 0) {
        const float* base = g_heat + b * HW;
        float s = base[o11];
        if (cv) s += base[o10];
        if (rv) {
            s += base[o01];
            if (cv) s += base[o00];
        }
        g_sal[b * NA + n] = 0.25f * s;
    }
}

// [rows,C]@[C,256] + bias -> LayerNorm -> l2norm. 8 rows per block, thread = p.
template <int C>
__global__ void proj_kernel(const float* __restrict__ wmat,
                            const float* __restrict__ bias,
                            const float* __restrict__ gamma,
                            const float* __restrict__ beta) {
    __shared__ float sRow[8 * C];
    __shared__ float sh[33];
    const float* samp = (C == CT) ? g_sampT : g_sampS;
    float* outp = (C == CT) ? g_ft : g_fs;
    int a0 = blockIdx.x * 8;
    int p = threadIdx.x;
    for (int i = threadIdx.x; i < 8 * C; i += 256) sRow[i] = samp[(size_t)a0 * C + i];
    __syncthreads();
    float acc[8];
#pragma unroll
    for (int i = 0; i < 8; ++i) acc[i] = 0.f;
    for (int c = 0; c < C; ++c) {
        float w = wmat[(size_t)c * NP + p];
#pragma unroll
        for (int i = 0; i < 8; ++i) acc[i] += sRow[i * C + c] * w;
    }
    float bi = bias[p], ga = gamma[p], be = beta[p];
#pragma unroll 1
    for (int i = 0; i < 8; ++i) {
        float x = acc[i] + bi;
        float mu = block_sum_256(x, sh) * (1.0f / NP);
        float d = x - mu;
        float var = block_sum_256(d * d, sh) * (1.0f / NP);
        float y = d * rsqrtf(var + 1e-5f) * ga + be;
        float nrm = sqrtf(block_sum_256(y * y, sh));
        y = y / fmaxf(nrm, 1e-12f);
        outp[(size_t)(a0 + i) * NP + p] = y;
    }
}

__global__ void gafd_kernel() {
    __shared__ float sh[33];
    float s = 0.f;
    const int total = NB * NA * NP;
    for (int i = blockIdx.x * blockDim.x + threadIdx.x; i < total;
         i += gridDim.x * blockDim.x) {
        float d = g_fs[i] - g_ft[i];
        s += d * d;
    }
    float bs = block_sum_256(s, sh);
    if (threadIdx.x == 0) atomicAdd(&g_gafd, bs);
}

__global__ void bd_kernel() {
    __shared__ float sh[33];
    int b = blockIdx.x;
    float s = g_sal[b * NA + threadIdx.x];
    float mx = block_max_256(s, sh);
    int bd = (s > 0.6f * mx) ? 1 : 0;
    g_bd[b * NA + threadIdx.x] = bd;
    float cnt = block_sum_256((float)bd, sh);
    if (threadIdx.x == 0) g_cnt[b] = (int)(cnt + 0.5f);
}

__global__ void abcd_kernel() {
    __shared__ float fsn[NP];
    __shared__ float sh[33];
    int blk = blockIdx.x;
    int b = blk >> 8, n = blk & 255;
    if (!g_bd[b * NA + n]) return;
    int t = threadIdx.x;
    float fv = g_fs[(size_t)(b * NA + n) * NP + t];
    float ftv = g_ft[(size_t)(b * NA + n) * NP + t];
    fsn[t] = fv;
    __syncthreads();
    float pos = block_sum_256(fv * ftv, sh) * 10.0f;  // /TAU
    const float4* fm = (const float4*)(g_fs + (size_t)(b * NA + t) * NP);
    float dm = 0.f;
#pragma unroll 4
    for (int q = 0; q < NP / 4; ++q) {
        float4 v = fm[q];
        dm += fsn[4 * q] * v.x + fsn[4 * q + 1] * v.y + fsn[4 * q + 2] * v.z +
              fsn[4 * q + 3] * v.w;
    }
    float val = g_bd[b * NA + t] ? -1e30f : dm * 10.0f;
    float mx = fmaxf(pos, block_max_256(val, sh));
    float e = (val < -1e29f) ? 0.f : expf(val - mx);
    float ssum = block_sum_256(e, sh) + expf(pos - mx);
    if (t == 0) atomicAdd(&g_abcd_b[b], mx + logf(ssum) - pos);
}

__global__ void final_kernel(float* __restrict__ out) {
    int t = threadIdx.x;
    float per = 0.f, valid = 0.f;
    if (t < NB) {
        int c = g_cnt[t];
        per = g_abcd_b[t] / fmaxf((float)c, 1.0f);
        valid = (c > 0 && c < NA) ? 1.0f : 0.0f;
    }
    float pv = per * valid;
#pragma unroll
    for (int o = 16; o; o >>= 1) {
        pv += __shfl_down_sync(0xffffffffu, pv, o);
        valid += __shfl_down_sync(0xffffffffu, valid, o);
    }
    if (t == 0) {
        float gafd = g_gafd * (1.0f / (NB * NA * NP));
        float abcd = (valid > 0.f) ? pv / valid : 0.f;
        out[0] = gafd + 0.5f * abcd;
        out[1] = gafd;
        out[2] = abcd;
    }
}

// ---------------- host launch ----------------
extern "C" void kernel_launch(void* const* d_in, const int* in_sizes, int n_in,
                              void* d_out, int out_size) {
    const float* T = (const float*)d_in[0];
    const float* Sf = (const float*)d_in[1];
    const float* w1 = (const float*)d_in[2];
    const float* b1 = (const float*)d_in[3];
    const float* w2 = (const float*)d_in[4];
    const float* b2 = (const float*)d_in[5];
    const float* tw = (const float*)d_in[6];
    const float* tb = (const float*)d_in[7];
    const float* tg = (const float*)d_in[8];
    const float* tbe = (const float*)d_in[9];
    const float* sw = (const float*)d_in[10];
    const float* sb = (const float*)d_in[11];
    const float* sg = (const float*)d_in[12];
    const float* sbe = (const float*)d_in[13];
    float* out = (float*)d_out;

    const int DSMEM = 2 * STAGE_BYTES;  // 221184
    static int s_attr_done = 0;
    if (!s_attr_done) {
        cudaFuncSetAttribute(convmma_kernel,
                             cudaFuncAttributeMaxDynamicSharedMemorySize, DSMEM);
        s_attr_done = 1;
    }

    reset_kernel<<<(NB * HW + 255) / 256, 256>>>();
    tprep_kernel<<<dim3(128, 32, 16), dim3(32, 8)>>>(T);
    wprep_kernel<<<(9 * CM * CT + 255) / 256, 256>>>(w1);
    convmma_kernel<<<dim3(2, 32, 16), 512, DSMEM>>>(b1, w2);
    softplus_kernel<<<NB * HW / 256, 256>>>(b2, out);
    score_kernel<<<16, 256>>>();
    topk_kernel<<<16, 512>>>();
    gather_kernel<<<NB * NA, 256>>>(T, Sf);
    proj_kernel<CT><<<512, 256>>>(tw, tb, tg, tbe);
    proj_kernel<CS><<<512, 256>>>(sw, sb, sg, sbe);
    gafd_kernel<<<256, 256>>>();
    bd_kernel<<<NB, 256>>>();
    abcd_kernel<<<NB * NA, 256>>>();
    final_kernel<<<1, 32>>>(out);
}

// round 13
// speedup vs baseline: 1.1223x; 1.0132x over previous
#include <cuda_runtime.h>
#include <cuda_fp16.h>
#include <math.h>
#include <stdint.h>

#define NB 16
#define CT 1024
#define CS 512
#define CM 512
#define HH 64
#define WW 64
#define HW 4096
#define NP 256
#define NA 256

// ---------------- scratch (device globals; no allocation) ----------------
__device__ float g_heatacc[NB * HW];  // conv+1x1 fused accumulator
__device__ float g_heat[NB * HW];
__device__ float g_score[NB * HW];
__device__ int   g_idx[NB * NA];
__device__ float g_sampT[NB * NA * CT];
__device__ float g_sampS[NB * NA * CS];
__device__ float g_sal[NB * NA];
__device__ float g_ft[NB * NA * NP];
__device__ float g_fs[NB * NA * NP];
__device__ int   g_bd[NB * NA];
__device__ int   g_cnt[NB];
__device__ float g_gafd;
__device__ float g_abcd_b[NB];

// fp16 hi/lo split tensors (lo pre-scaled by 512)
__device__ __align__(16) __half g_Thi[NB * HW * CT];      // [b][p][ci]
__device__ __align__(16) __half g_Tlo[NB * HW * CT];
__device__ __align__(16) __half g_Whi[9 * CM * CT];       // [tap][co][ci]
__device__ __align__(16) __half g_Wlo[9 * CM * CT];

#define LO_SCALE 512.0f
#define LO_INV (1.0f / 512.0f)

// ---------------- sm_80-class PTX helpers (compile on compute_103) --------
__device__ __forceinline__ uint32_t smem_to_u32(const void* smem_ptr) {
    uint32_t addr;
    asm("{ .reg .u64 tmp; cvta.to.shared.u64 tmp, %1; cvt.u32.u64 %0, tmp; }"
        : "=r"(addr) : "l"(smem_ptr));
    return addr;
}
__device__ __forceinline__ void cp16(uint32_t dst, const void* src, bool ok) {
    int sz = ok ? 16 : 0;
    asm volatile("cp.async.cg.shared.global [%0], [%1], 16, %2;"
                 :: "r"(dst), "l"(src), "r"(sz) : "memory");
}
#define CP_COMMIT() asm volatile("cp.async.commit_group;" ::: "memory")
#define CP_WAIT0()  asm volatile("cp.async.wait_group 0;" ::: "memory")

__device__ __forceinline__ void ldsm4(uint32_t* r, uint32_t addr) {
    asm volatile("ldmatrix.sync.aligned.m8n8.x4.shared.b16 {%0,%1,%2,%3}, [%4];"
                 : "=r"(r[0]), "=r"(r[1]), "=r"(r[2]), "=r"(r[3]) : "r"(addr));
}
// f32-accumulator fp16 MMA (main pass)
__device__ __forceinline__ void mma_f32(float* c, const uint32_t* a,
                                        uint32_t b0, uint32_t b1) {
    asm volatile(
        "mma.sync.aligned.m16n8k16.row.col.f32.f16.f16.f32 "
        "{%0,%1,%2,%3}, {%4,%5,%6,%7}, {%8,%9}, {%0,%1,%2,%3};"
        : "+f"(c[0]), "+f"(c[1]), "+f"(c[2]), "+f"(c[3])
        : "r"(a[0]), "r"(a[1]), "r"(a[2]), "r"(a[3]), "r"(b0), "r"(b1));
}
// f16-accumulator fp16 MMA (correction passes; 2 packed regs)
__device__ __forceinline__ void mma_f16(uint32_t* c, const uint32_t* a,
                                        uint32_t b0, uint32_t b1) {
    asm volatile(
        "mma.sync.aligned.m16n8k16.row.col.f16.f16.f16.f16 "
        "{%0,%1}, {%2,%3,%4,%5}, {%6,%7}, {%0,%1};"
        : "+r"(c[0]), "+r"(c[1])
        : "r"(a[0]), "r"(a[1]), "r"(a[2]), "r"(a[3]), "r"(b0), "r"(b1));
}

// ---------------- generic helpers ----------------
__device__ __forceinline__ float block_sum_256(float v, float* sh) {
#pragma unroll
    for (int o = 16; o; o >>= 1) v += __shfl_down_sync(0xffffffffu, v, o);
    __syncthreads();
    if ((threadIdx.x & 31) == 0) sh[threadIdx.x >> 5] = v;
    __syncthreads();
    if (threadIdx.x == 0) {
        float t = 0.f;
        for (int i = 0; i < 8; ++i) t += sh[i];
        sh[32] = t;
    }
    __syncthreads();
    return sh[32];
}

__device__ __forceinline__ float block_max_256(float v, float* sh) {
#pragma unroll
    for (int o = 16; o; o >>= 1) v = fmaxf(v, __shfl_down_sync(0xffffffffu, v, o));
    __syncthreads();
    if ((threadIdx.x & 31) == 0) sh[threadIdx.x >> 5] = v;
    __syncthreads();
    if (threadIdx.x == 0) {
        float t = sh[0];
        for (int i = 1; i < 8; ++i) t = fmaxf(t, sh[i]);
        sh[32] = t;
    }
    __syncthreads();
    return sh[32];
}

__device__ __forceinline__ void threefry2x32(unsigned k0, unsigned k1,
                                             unsigned x0, unsigned x1,
                                             unsigned& o0, unsigned& o1) {
    unsigned ks[3] = {k0, k1, k0 ^ k1 ^ 0x1BD11BDAu};
    x0 += ks[0];
    x1 += ks[1];
    const int R[5][4] = {{13, 15, 26, 6}, {17, 29, 16, 24}, {13, 15, 26, 6},
                         {17, 29, 16, 24}, {13, 15, 26, 6}};
#pragma unroll
    for (int g = 0; g < 5; ++g) {
#pragma unroll
        for (int q = 0; q < 4; ++q) {
            x0 += x1;
            int rr = R[g][q];
            x1 = (x1 << rr) | (x1 >> (32 - rr));
            x1 ^= x0;
        }
        x0 += ks[(g + 1) % 3];
        x1 += ks[(g + 2) % 3] + (unsigned)(g + 1);
    }
    o0 = x0;
    o1 = x1;
}

// ---------------- kernels ----------------
__global__ void reset_kernel() {
    int i = blockIdx.x * blockDim.x + threadIdx.x;
    if (i < NB * HW) g_heatacc[i] = 0.f;
    if (i == 0) g_gafd = 0.f;
    if (i < NB) g_abcd_b[i] = 0.f;
}

// transpose + fp16 split of teacher feat: T[b][ci][p] -> Thi/Tlo[b][p][ci]
__global__ void tprep_kernel(const float* __restrict__ T) {
    __shared__ float tile[32][33];
    int b = blockIdx.z, p0 = blockIdx.x * 32, c0 = blockIdx.y * 32;
    int tx = threadIdx.x, ty = threadIdx.y;
    for (int i = ty; i < 32; i += 8)
        tile[i][tx] = T[((size_t)(b * CT + c0 + i)) * HW + p0 + tx];
    __syncthreads();
    for (int i = ty; i < 32; i += 8) {
        float v = tile[tx][i];
        __half h = __float2half_rn(v);
        float hf = __half2float(h);
        size_t o = ((size_t)b * HW + p0 + i) * CT + c0 + tx;
        g_Thi[o] = h;
        g_Tlo[o] = __float2half_rn((v - hf) * LO_SCALE);
    }
}

// weights split: W1[co][ci][tap] -> Whi/Wlo[tap][co][ci]
__global__ void wprep_kernel(const float* __restrict__ W1) {
    int idx = blockIdx.x * blockDim.x + threadIdx.x;
    if (idx >= 9 * CM * CT) return;
    int ci = idx & (CT - 1);
    int rest = idx >> 10;
    int co = rest & (CM - 1);
    int tap = rest >> 9;
    float w = W1[((size_t)co * CT + ci) * 9 + tap];
    __half h = __float2half_rn(w);
    float hf = __half2float(h);
    g_Whi[idx] = h;
    g_Wlo[idx] = __float2half_rn((w - hf) * LO_SCALE);
}

// conv1 (fp16x3 implicit GEMM via mma.sync) fused with the 1x1 conv.
// Main pass f32-acc; correction passes share a f16 accumulator (x512 scaled).
// CTA: 512 threads, 128 px x 256 co. 2-stage cp.async, 1 sync/chunk.
#define ROWB 144                      // bytes per smem row (64 fp16 + 8 pad)
#define A_BYTES (128 * ROWB)          // 18432
#define B_BYTES (256 * ROWB)          // 36864
#define STAGE_BYTES (2 * A_BYTES + 2 * B_BYTES)  // 110592
__global__ __launch_bounds__(512, 1)
void convmma_kernel(const float* __restrict__ b1, const float* __restrict__ w2) {
    extern __shared__ char dsm[];
    uint32_t sb = smem_to_u32(dsm);
    int tid = threadIdx.x, lane = tid & 31, wid = tid >> 5;
    int co0 = blockIdx.x * 256;
    int pixtile = blockIdx.y;
    int bb = blockIdx.z;
    int y0 = pixtile * 2, p0 = pixtile * 128;
    int wm = wid & 3, wn = wid >> 2;   // 4 M-groups of 32 px; 4 N-groups of 64 co

    float acc[2][8][4];
    uint32_t corr[2][8][2];            // packed f16x2 correction accumulators
#pragma unroll
    for (int i = 0; i < 2; ++i)
#pragma unroll
        for (int j = 0; j < 8; ++j) {
#pragma unroll
            for (int k = 0; k < 4; ++k) acc[i][j][k] = 0.f;
            corr[i][j][0] = 0u;
            corr[i][j][1] = 0u;
        }

    auto load_chunk = [&](int c, int s) {
        int tap = c >> 4, kc = c & 15;
        int dy = tap / 3 - 1, dx = tap % 3 - 1;
        int ci0 = kc * 64;
        uint32_t base = sb + (uint32_t)s * STAGE_BYTES;
#pragma unroll
        for (int i = 0; i < 2; ++i) {
            int u = i * 512 + tid;
            int r = u >> 3, seg = u & 7;
            int ys = y0 + (r >> 6) + dy;
            int xs = (r & 63) + dx;
            bool ok = ((unsigned)ys < 64u) && ((unsigned)xs < 64u);
            int ysc = ok ? ys : 0, xsc = ok ? xs : 0;
            size_t g = ((size_t)(bb * HW + ysc * 64 + xsc)) * CT + ci0 + seg * 8;
            uint32_t off = (uint32_t)(r * ROWB + seg * 16);
            cp16(base + off, g_Thi + g, ok);
            cp16(base + A_BYTES + off, g_Tlo + g, ok);
        }
#pragma unroll
        for (int i = 0; i < 4; ++i) {
            int u = i * 512 + tid;
            int r = u >> 3, seg = u & 7;
            size_t g = ((size_t)(tap * CM + co0 + r)) * CT + ci0 + seg * 8;
            uint32_t off = (uint32_t)(r * ROWB + seg * 16);
            cp16(base + 2 * A_BYTES + off, g_Whi + g, true);
            cp16(base + 2 * A_BYTES + B_BYTES + off, g_Wlo + g, true);
        }
    };

    auto compute = [&](int s) {
        uint32_t Ah = sb + (uint32_t)s * STAGE_BYTES;
        uint32_t Al = Ah + A_BYTES;
        uint32_t Bh = Ah + 2 * A_BYTES;
        uint32_t Bl = Bh + B_BYTES;
#pragma unroll
        for (int ks = 0; ks < 4; ++ks) {
            uint32_t aH[2][4], aL[2][4];
#pragma unroll
            for (int t = 0; t < 2; ++t) {
                uint32_t ra = (uint32_t)((wm * 32 + t * 16 + (lane & 15)) * ROWB +
                                         ks * 32 + (lane >> 4) * 16);
                ldsm4(aH[t], Ah + ra);
                ldsm4(aL[t], Al + ra);
            }
            // loop 1: bH -> main f32 pass + Alo x Bhi f16 correction
#pragma unroll
            for (int nt = 0; nt < 4; ++nt) {
                uint32_t rb = (uint32_t)((wn * 64 + nt * 16 + (lane & 15)) * ROWB +
                                         ks * 32 + (lane >> 4) * 16);
                uint32_t bb4[4];
                ldsm4(bb4, Bh + rb);
#pragma unroll
                for (int mi = 0; mi < 2; ++mi) {
                    mma_f32(acc[mi][2 * nt], aH[mi], bb4[0], bb4[2]);
                    mma_f32(acc[mi][2 * nt + 1], aH[mi], bb4[1], bb4[3]);
                }
#pragma unroll
                for (int mi = 0; mi < 2; ++mi) {
                    mma_f16(corr[mi][2 * nt], aL[mi], bb4[0], bb4[2]);
                    mma_f16(corr[mi][2 * nt + 1], aL[mi], bb4[1], bb4[3]);
                }
            }
            // loop 2: bL -> Ahi x Blo f16 correction
#pragma unroll
            for (int nt = 0; nt < 4; ++nt) {
                uint32_t rb = (uint32_t)((wn * 64 + nt * 16 + (lane & 15)) * ROWB +
                                         ks * 32 + (lane >> 4) * 16);
                uint32_t bb4[4];
                ldsm4(bb4, Bl + rb);
#pragma unroll
                for (int mi = 0; mi < 2; ++mi) {
                    mma_f16(corr[mi][2 * nt], aH[mi], bb4[0], bb4[2]);
                    mma_f16(corr[mi][2 * nt + 1], aH[mi], bb4[1], bb4[3]);
                }
            }
        }
    };

    load_chunk(0, 0);
    CP_COMMIT();
#pragma unroll 1
    for (int c = 0; c < 144; ++c) {
        int s = c & 1;
        CP_WAIT0();
        __syncthreads();
        if (c + 1 < 144) {
            load_chunk(c + 1, s ^ 1);
            CP_COMMIT();
        }
        compute(s);
    }

    // merge corrections: acc += f16(corr)/512
#pragma unroll
    for (int mi = 0; mi < 2; ++mi)
#pragma unroll
        for (int j = 0; j < 8; ++j) {
            __half2 c01 = *reinterpret_cast<__half2*>(&corr[mi][j][0]);
            __half2 c23 = *reinterpret_cast<__half2*>(&corr[mi][j][1]);
            acc[mi][j][0] += __half2float(__low2half(c01)) * LO_INV;
            acc[mi][j][1] += __half2float(__high2half(c01)) * LO_INV;
            acc[mi][j][2] += __half2float(__low2half(c23)) * LO_INV;
            acc[mi][j][3] += __half2float(__high2half(c23)) * LO_INV;
        }

    // fused epilogue: h = relu(acc + b1); heatacc[p] += sum_co h * w2[co]
    float hp[2][2] = {{0.f, 0.f}, {0.f, 0.f}};
#pragma unroll
    for (int mi = 0; mi < 2; ++mi) {
#pragma unroll
        for (int nt = 0; nt < 8; ++nt) {
            int co = co0 + wn * 64 + nt * 8 + (lane & 3) * 2;
            float bv0 = b1[co], bv1 = b1[co + 1];
            float w20 = w2[co], w21 = w2[co + 1];
            float h00 = fmaxf(acc[mi][nt][0] + bv0, 0.f);
            float h01 = fmaxf(acc[mi][nt][1] + bv1, 0.f);
            float h10 = fmaxf(acc[mi][nt][2] + bv0, 0.f);
            float h11 = fmaxf(acc[mi][nt][3] + bv1, 0.f);
            hp[mi][0] += h00 * w20 + h01 * w21;
            hp[mi][1] += h10 * w20 + h11 * w21;
        }
    }
#pragma unroll
    for (int mi = 0; mi < 2; ++mi) {
        int r0 = wm * 32 + mi * 16 + (lane >> 2);
        atomicAdd(&g_heatacc[bb * HW + p0 + r0], hp[mi][0]);
        atomicAdd(&g_heatacc[bb * HW + p0 + r0 + 8], hp[mi][1]);
    }
}

// softplus(acc + b2) -> heatmap (scratch + output)
__global__ void softplus_kernel(const float* __restrict__ b2,
                                float* __restrict__ out) {
    int i = blockIdx.x * 256 + threadIdx.x;
    float a = g_heatacc[i] + b2[0];
    float sp = fmaxf(a, 0.f) + log1pf(expf(-fabsf(a)));
    g_heat[i] = sp;
    out[3 + i] = sp;
}

// per-batch: normalize to prob, add JAX (partitionable threefry) Gumbel -> score
__global__ void score_kernel() {
    __shared__ float sh[33];
    int b = blockIdx.x;
    float s = 0.f;
    for (int p = threadIdx.x; p < HW; p += 256) s += g_heat[b * HW + p];
    float S = block_sum_256(s, sh);
    for (int p = threadIdx.x; p < HW; p += 256) {
        unsigned gi = (unsigned)(b * HW + p);
        unsigned o0, o1;
        threefry2x32(0u, 42u, 0u, gi, o0, o1);
        unsigned bits = o0 ^ o1;
        float f = __uint_as_float((bits >> 9) | 0x3f800000u) - 1.0f;
        float u = fmaxf(1e-8f, f * (1.0f - 1e-8f) + 1e-8f);
        float gum = -logf(-logf(u));
        g_score[gi] = logf(g_heat[gi] / (S + 1e-6f) + 1e-12f) + gum;
    }
}

// top-256 per batch via in-smem bitonic sort
__global__ void topk_kernel() {
    __shared__ float key[HW];
    __shared__ int val[HW];
    int b = blockIdx.x;
    for (int i = threadIdx.x; i < HW; i += blockDim.x) {
        key[i] = -g_score[b * HW + i];
        val[i] = i;
    }
    for (int k = 2; k <= HW; k <<= 1)
        for (int j = k >> 1; j > 0; j >>= 1) {
            __syncthreads();
            for (int i = threadIdx.x; i < HW; i += blockDim.x) {
                int p = i ^ j;
                if (p > i) {
                    bool up = ((i & k) == 0);
                    float ki = key[i], kp = key[p];
                    if ((ki > kp) == up) {
                        key[i] = kp;
                        key[p] = ki;
                        int t = val[i];
                        val[i] = val[p];
                        val[p] = t;
                    }
                }
            }
        }
    __syncthreads();
    for (int i = threadIdx.x; i < NA; i += blockDim.x) g_idx[b * NA + i] = val[i];
}

// bilinear sample == 0.25 * sum of 4 pixels with zero pad
__global__ void gather_kernel(const float* __restrict__ T,
                              const float* __restrict__ Sf) {
    int blk = blockIdx.x;
    int b = blk >> 8, n = blk & 255;
    int idx = g_idx[b * NA + n];
    int r = idx >> 6, c = idx & 63;
    bool rv = r > 0, cv = c > 0;
    int o11 = r * WW + c, o10 = o11 - 1, o01 = o11 - WW, o00 = o01 - 1;
    for (int ch = threadIdx.x; ch < CT; ch += blockDim.x) {
        const float* base = T + (size_t)(b * CT + ch) * HW;
        float s = base[o11];
        if (cv) s += base[o10];
        if (rv) {
            s += base[o01];
            if (cv) s += base[o00];
        }
        g_sampT[(size_t)(b * NA + n) * CT + ch] = 0.25f * s;
    }
    for (int ch = threadIdx.x; ch < CS; ch += blockDim.x) {
        const float* base = Sf + (size_t)(b * CS + ch) * HW;
        float s = base[o11];
        if (cv) s += base[o10];
        if (rv) {
            s += base[o01];
            if (cv) s += base[o00];
        }
        g_sampS[(size_t)(b * NA + n) * CS + ch] = 0.25f * s;
    }
    if (threadIdx.x == 0) {
        const float* base = g_heat + b * HW;
        float s = base[o11];
        if (cv) s += base[o10];
        if (rv) {
            s += base[o01];
            if (cv) s += base[o00];
        }
        g_sal[b * NA + n] = 0.25f * s;
    }
}

// [rows,C]@[C,256] + bias -> LayerNorm -> l2norm. 8 rows per block, thread = p.
template <int C>
__global__ void proj_kernel(const float* __restrict__ wmat,
                            const float* __restrict__ bias,
                            const float* __restrict__ gamma,
                            const float* __restrict__ beta) {
    __shared__ float sRow[8 * C];
    __shared__ float sh[33];
    const float* samp = (C == CT) ? g_sampT : g_sampS;
    float* outp = (C == CT) ? g_ft : g_fs;
    int a0 = blockIdx.x * 8;
    int p = threadIdx.x;
    for (int i = threadIdx.x; i < 8 * C; i += 256) sRow[i] = samp[(size_t)a0 * C + i];
    __syncthreads();
    float acc[8];
#pragma unroll
    for (int i = 0; i < 8; ++i) acc[i] = 0.f;
    for (int c = 0; c < C; ++c) {
        float w = wmat[(size_t)c * NP + p];
#pragma unroll
        for (int i = 0; i < 8; ++i) acc[i] += sRow[i * C + c] * w;
    }
    float bi = bias[p], ga = gamma[p], be = beta[p];
#pragma unroll 1
    for (int i = 0; i < 8; ++i) {
        float x = acc[i] + bi;
        float mu = block_sum_256(x, sh) * (1.0f / NP);
        float d = x - mu;
        float var = block_sum_256(d * d, sh) * (1.0f / NP);
        float y = d * rsqrtf(var + 1e-5f) * ga + be;
        float nrm = sqrtf(block_sum_256(y * y, sh));
        y = y / fmaxf(nrm, 1e-12f);
        outp[(size_t)(a0 + i) * NP + p] = y;
    }
}

__global__ void gafd_kernel() {
    __shared__ float sh[33];
    float s = 0.f;
    const int total = NB * NA * NP;
    for (int i = blockIdx.x * blockDim.x + threadIdx.x; i < total;
         i += gridDim.x * blockDim.x) {
        float d = g_fs[i] - g_ft[i];
        s += d * d;
    }
    float bs = block_sum_256(s, sh);
    if (threadIdx.x == 0) atomicAdd(&g_gafd, bs);
}

__global__ void bd_kernel() {
    __shared__ float sh[33];
    int b = blockIdx.x;
    float s = g_sal[b * NA + threadIdx.x];
    float mx = block_max_256(s, sh);
    int bd = (s > 0.6f * mx) ? 1 : 0;
    g_bd[b * NA + threadIdx.x] = bd;
    float cnt = block_sum_256((float)bd, sh);
    if (threadIdx.x == 0) g_cnt[b] = (int)(cnt + 0.5f);
}

__global__ void abcd_kernel() {
    __shared__ float fsn[NP];
    __shared__ float sh[33];
    int blk = blockIdx.x;
    int b = blk >> 8, n = blk & 255;
    if (!g_bd[b * NA + n]) return;
    int t = threadIdx.x;
    float fv = g_fs[(size_t)(b * NA + n) * NP + t];
    float ftv = g_ft[(size_t)(b * NA + n) * NP + t];
    fsn[t] = fv;
    __syncthreads();
    float pos = block_sum_256(fv * ftv, sh) * 10.0f;  // /TAU
    const float4* fm = (const float4*)(g_fs + (size_t)(b * NA + t) * NP);
    float dm = 0.f;
#pragma unroll 4
    for (int q = 0; q < NP / 4; ++q) {
        float4 v = fm[q];
        dm += fsn[4 * q] * v.x + fsn[4 * q + 1] * v.y + fsn[4 * q + 2] * v.z +
              fsn[4 * q + 3] * v.w;
    }
    float val = g_bd[b * NA + t] ? -1e30f : dm * 10.0f;
    float mx = fmaxf(pos, block_max_256(val, sh));
    float e = (val < -1e29f) ? 0.f : expf(val - mx);
    float ssum = block_sum_256(e, sh) + expf(pos - mx);
    if (t == 0) atomicAdd(&g_abcd_b[b], mx + logf(ssum) - pos);
}

__global__ void final_kernel(float* __restrict__ out) {
    int t = threadIdx.x;
    float per = 0.f, valid = 0.f;
    if (t < NB) {
        int c = g_cnt[t];
        per = g_abcd_b[t] / fmaxf((float)c, 1.0f);
        valid = (c > 0 && c < NA) ? 1.0f : 0.0f;
    }
    float pv = per * valid;
#pragma unroll
    for (int o = 16; o; o >>= 1) {
        pv += __shfl_down_sync(0xffffffffu, pv, o);
        valid += __shfl_down_sync(0xffffffffu, valid, o);
    }
    if (t == 0) {
        float gafd = g_gafd * (1.0f / (NB * NA * NP));
        float abcd = (valid > 0.f) ? pv / valid : 0.f;
        out[0] = gafd + 0.5f * abcd;
        out[1] = gafd;
        out[2] = abcd;
    }
}

// ---------------- host launch ----------------
extern "C" void kernel_launch(void* const* d_in, const int* in_sizes, int n_in,
                              void* d_out, int out_size) {
    const float* T = (const float*)d_in[0];
    const float* Sf = (const float*)d_in[1];
    const float* w1 = (const float*)d_in[2];
    const float* b1 = (const float*)d_in[3];
    const float* w2 = (const float*)d_in[4];
    const float* b2 = (const float*)d_in[5];
    const float* tw = (const float*)d_in[6];
    const float* tb = (const float*)d_in[7];
    const float* tg = (const float*)d_in[8];
    const float* tbe = (const float*)d_in[9];
    const float* sw = (const float*)d_in[10];
    const float* sb = (const float*)d_in[11];
    const float* sg = (const float*)d_in[12];
    const float* sbe = (const float*)d_in[13];
    float* out = (float*)d_out;

    const int DSMEM = 2 * STAGE_BYTES;  // 221184
    static int s_attr_done = 0;
    if (!s_attr_done) {
        cudaFuncSetAttribute(convmma_kernel,
                             cudaFuncAttributeMaxDynamicSharedMemorySize, DSMEM);
        s_attr_done = 1;
    }

    reset_kernel<<<(NB * HW + 255) / 256, 256>>>();
    tprep_kernel<<<dim3(128, 32, 16), dim3(32, 8)>>>(T);
    wprep_kernel<<<(9 * CM * CT + 255) / 256, 256>>>(w1);
    convmma_kernel<<<dim3(2, 32, 16), 512, DSMEM>>>(b1, w2);
    softplus_kernel<<<NB * HW / 256, 256>>>(b2, out);
    score_kernel<<<16, 256>>>();
    topk_kernel<<<16, 512>>>();
    gather_kernel<<<NB * NA, 256>>>(T, Sf);
    proj_kernel<CT><<<512, 256>>>(tw, tb, tg, tbe);
    proj_kernel<CS><<<512, 256>>>(sw, sb, sg, sbe);
    gafd_kernel<<<256, 256>>>();
    bd_kernel<<<NB, 256>>>();
    abcd_kernel<<<NB * NA, 256>>>();
    final_kernel<<<1, 32>>>(out);
}

// round 14
// speedup vs baseline: 1.4167x; 1.2623x over previous
#include <cuda_runtime.h>
#include <cuda_fp16.h>
#include <math.h>
#include <stdint.h>

#define NB 16
#define CT 1024
#define CS 512
#define CM 512
#define HH 64
#define WW 64
#define HW 4096
#define NP 256
#define NA 256

// ---------------- scratch (device globals; no allocation) ----------------
__device__ float g_heatacc[NB * HW];  // conv+1x1 fused accumulator
__device__ float g_heat[NB * HW];
__device__ float g_score[NB * HW];
__device__ int   g_idx[NB * NA];
__device__ float g_sampT[NB * NA * CT];
__device__ float g_sampS[NB * NA * CS];
__device__ float g_sal[NB * NA];
__device__ float g_ft[NB * NA * NP];
__device__ float g_fs[NB * NA * NP];
__device__ int   g_bd[NB * NA];
__device__ int   g_cnt[NB];
__device__ float g_gafd;
__device__ float g_abcd_b[NB];

// fp16 split: activations hi/lo (lo pre-scaled by 512), weights fp16 only
__device__ __align__(16) __half g_Thi[NB * HW * CT];      // [b][p][ci]
__device__ __align__(16) __half g_Tlo[NB * HW * CT];
__device__ __align__(16) __half g_Whi[9 * CM * CT];       // [tap][co][ci]

#define LO_SCALE 512.0f
#define LO_INV (1.0f / 512.0f)

// ---------------- sm_80-class PTX helpers (compile on compute_103) --------
__device__ __forceinline__ uint32_t smem_to_u32(const void* smem_ptr) {
    uint32_t addr;
    asm("{ .reg .u64 tmp; cvta.to.shared.u64 tmp, %1; cvt.u32.u64 %0, tmp; }"
        : "=r"(addr) : "l"(smem_ptr));
    return addr;
}
__device__ __forceinline__ void cp16(uint32_t dst, const void* src, bool ok) {
    int sz = ok ? 16 : 0;
    asm volatile("cp.async.cg.shared.global [%0], [%1], 16, %2;"
                 :: "r"(dst), "l"(src), "r"(sz) : "memory");
}
#define CP_COMMIT() asm volatile("cp.async.commit_group;" ::: "memory")
#define CP_WAIT1()  asm volatile("cp.async.wait_group 1;" ::: "memory")
#define CP_WAIT0()  asm volatile("cp.async.wait_group 0;" ::: "memory")

__device__ __forceinline__ void ldsm4(uint32_t* r, uint32_t addr) {
    asm volatile("ldmatrix.sync.aligned.m8n8.x4.shared.b16 {%0,%1,%2,%3}, [%4];"
                 : "=r"(r[0]), "=r"(r[1]), "=r"(r[2]), "=r"(r[3]) : "r"(addr));
}
// f32-accumulator fp16 MMA (main pass)
__device__ __forceinline__ void mma_f32(float* c, const uint32_t* a,
                                        uint32_t b0, uint32_t b1) {
    asm volatile(
        "mma.sync.aligned.m16n8k16.row.col.f32.f16.f16.f32 "
        "{%0,%1,%2,%3}, {%4,%5,%6,%7}, {%8,%9}, {%0,%1,%2,%3};"
        : "+f"(c[0]), "+f"(c[1]), "+f"(c[2]), "+f"(c[3])
        : "r"(a[0]), "r"(a[1]), "r"(a[2]), "r"(a[3]), "r"(b0), "r"(b1));
}
// f16-accumulator fp16 MMA (activation-lo correction pass)
__device__ __forceinline__ void mma_f16(uint32_t* c, const uint32_t* a,
                                        uint32_t b0, uint32_t b1) {
    asm volatile(
        "mma.sync.aligned.m16n8k16.row.col.f16.f16.f16.f16 "
        "{%0,%1}, {%2,%3,%4,%5}, {%6,%7}, {%0,%1};"
        : "+r"(c[0]), "+r"(c[1])
        : "r"(a[0]), "r"(a[1]), "r"(a[2]), "r"(a[3]), "r"(b0), "r"(b1));
}

// ---------------- generic helpers ----------------
__device__ __forceinline__ float block_sum_256(float v, float* sh) {
#pragma unroll
    for (int o = 16; o; o >>= 1) v += __shfl_down_sync(0xffffffffu, v, o);
    __syncthreads();
    if ((threadIdx.x & 31) == 0) sh[threadIdx.x >> 5] = v;
    __syncthreads();
    if (threadIdx.x == 0) {
        float t = 0.f;
        for (int i = 0; i < 8; ++i) t += sh[i];
        sh[32] = t;
    }
    __syncthreads();
    return sh[32];
}

__device__ __forceinline__ float block_max_256(float v, float* sh) {
#pragma unroll
    for (int o = 16; o; o >>= 1) v = fmaxf(v, __shfl_down_sync(0xffffffffu, v, o));
    __syncthreads();
    if ((threadIdx.x & 31) == 0) sh[threadIdx.x >> 5] = v;
    __syncthreads();
    if (threadIdx.x == 0) {
        float t = sh[0];
        for (int i = 1; i < 8; ++i) t = fmaxf(t, sh[i]);
        sh[32] = t;
    }
    __syncthreads();
    return sh[32];
}

__device__ __forceinline__ void threefry2x32(unsigned k0, unsigned k1,
                                             unsigned x0, unsigned x1,
                                             unsigned& o0, unsigned& o1) {
    unsigned ks[3] = {k0, k1, k0 ^ k1 ^ 0x1BD11BDAu};
    x0 += ks[0];
    x1 += ks[1];
    const int R[5][4] = {{13, 15, 26, 6}, {17, 29, 16, 24}, {13, 15, 26, 6},
                         {17, 29, 16, 24}, {13, 15, 26, 6}};
#pragma unroll
    for (int g = 0; g < 5; ++g) {
#pragma unroll
        for (int q = 0; q < 4; ++q) {
            x0 += x1;
            int rr = R[g][q];
            x1 = (x1 << rr) | (x1 >> (32 - rr));
            x1 ^= x0;
        }
        x0 += ks[(g + 1) % 3];
        x1 += ks[(g + 2) % 3] + (unsigned)(g + 1);
    }
    o0 = x0;
    o1 = x1;
}

// ---------------- kernels ----------------
__global__ void reset_kernel() {
    int i = blockIdx.x * blockDim.x + threadIdx.x;
    if (i < NB * HW) g_heatacc[i] = 0.f;
    if (i == 0) g_gafd = 0.f;
    if (i < NB) g_abcd_b[i] = 0.f;
}

// transpose + fp16 split of teacher feat: T[b][ci][p] -> Thi/Tlo[b][p][ci]
__global__ void tprep_kernel(const float* __restrict__ T) {
    __shared__ float tile[32][33];
    int b = blockIdx.z, p0 = blockIdx.x * 32, c0 = blockIdx.y * 32;
    int tx = threadIdx.x, ty = threadIdx.y;
    for (int i = ty; i < 32; i += 8)
        tile[i][tx] = T[((size_t)(b * CT + c0 + i)) * HW + p0 + tx];
    __syncthreads();
    for (int i = ty; i < 32; i += 8) {
        float v = tile[tx][i];
        __half h = __float2half_rn(v);
        float hf = __half2float(h);
        size_t o = ((size_t)b * HW + p0 + i) * CT + c0 + tx;
        g_Thi[o] = h;
        g_Tlo[o] = __float2half_rn((v - hf) * LO_SCALE);
    }
}

// weights: W1[co][ci][tap] -> Whi[tap][co][ci] (fp16 rn)
__global__ void wprep_kernel(const float* __restrict__ W1) {
    int idx = blockIdx.x * blockDim.x + threadIdx.x;
    if (idx >= 9 * CM * CT) return;
    int ci = idx & (CT - 1);
    int rest = idx >> 10;
    int co = rest & (CM - 1);
    int tap = rest >> 9;
    float w = W1[((size_t)co * CT + ci) * 9 + tap];
    g_Whi[idx] = __float2half_rn(w);
}

// conv1 (fp16x2 implicit GEMM via mma.sync) fused with the 1x1 conv.
// A split hi/lo (lo x512, f16-acc correction); B plain fp16.
// CTA: 512 threads, 128 px x 256 co. 3-stage cp.async, 1 sync/chunk.
#define ROWB 144                      // bytes per smem row (64 fp16 + 8 pad)
#define A_BYTES (128 * ROWB)          // 18432
#define B_BYTES (256 * ROWB)          // 36864
#define STAGE_BYTES (2 * A_BYTES + B_BYTES)  // 73728
#define NSTAGE 3
__global__ __launch_bounds__(512, 1)
void convmma_kernel(const float* __restrict__ b1, const float* __restrict__ w2) {
    extern __shared__ char dsm[];
    uint32_t sb = smem_to_u32(dsm);
    int tid = threadIdx.x, lane = tid & 31, wid = tid >> 5;
    int co0 = blockIdx.x * 256;
    int pixtile = blockIdx.y;
    int bb = blockIdx.z;
    int y0 = pixtile * 2, p0 = pixtile * 128;
    int wm = wid & 3, wn = wid >> 2;   // 4 M-groups of 32 px; 4 N-groups of 64 co

    float acc[2][8][4];
    uint32_t corr[2][8][2];            // packed f16x2 correction accumulators
#pragma unroll
    for (int i = 0; i < 2; ++i)
#pragma unroll
        for (int j = 0; j < 8; ++j) {
#pragma unroll
            for (int k = 0; k < 4; ++k) acc[i][j][k] = 0.f;
            corr[i][j][0] = 0u;
            corr[i][j][1] = 0u;
        }

    auto load_chunk = [&](int c, int s) {
        int tap = c >> 4, kc = c & 15;
        int dy = tap / 3 - 1, dx = tap % 3 - 1;
        int ci0 = kc * 64;
        uint32_t base = sb + (uint32_t)s * STAGE_BYTES;
        // A: 128 pixel rows x 64 ci, shifted + zero-masked (hi @0, lo @A_BYTES)
#pragma unroll
        for (int i = 0; i < 2; ++i) {
            int u = i * 512 + tid;
            int r = u >> 3, seg = u & 7;
            int ys = y0 + (r >> 6) + dy;
            int xs = (r & 63) + dx;
            bool ok = ((unsigned)ys < 64u) && ((unsigned)xs < 64u);
            int ysc = ok ? ys : 0, xsc = ok ? xs : 0;
            size_t g = ((size_t)(bb * HW + ysc * 64 + xsc)) * CT + ci0 + seg * 8;
            uint32_t off = (uint32_t)(r * ROWB + seg * 16);
            cp16(base + off, g_Thi + g, ok);
            cp16(base + A_BYTES + off, g_Tlo + g, ok);
        }
        // B: 256 co rows x 64 ci (hi only, @2*A_BYTES)
#pragma unroll
        for (int i = 0; i < 4; ++i) {
            int u = i * 512 + tid;
            int r = u >> 3, seg = u & 7;
            size_t g = ((size_t)(tap * CM + co0 + r)) * CT + ci0 + seg * 8;
            uint32_t off = (uint32_t)(r * ROWB + seg * 16);
            cp16(base + 2 * A_BYTES + off, g_Whi + g, true);
        }
    };

    auto compute = [&](int s) {
        uint32_t Ah = sb + (uint32_t)s * STAGE_BYTES;
        uint32_t Al = Ah + A_BYTES;
        uint32_t Bh = Ah + 2 * A_BYTES;
#pragma unroll
        for (int ks = 0; ks < 4; ++ks) {
            uint32_t aH[2][4], aL[2][4];
#pragma unroll
            for (int t = 0; t < 2; ++t) {
                uint32_t ra = (uint32_t)((wm * 32 + t * 16 + (lane & 15)) * ROWB +
                                         ks * 32 + (lane >> 4) * 16);
                ldsm4(aH[t], Ah + ra);
                ldsm4(aL[t], Al + ra);
            }
#pragma unroll
            for (int nt = 0; nt < 4; ++nt) {
                uint32_t rb = (uint32_t)((wn * 64 + nt * 16 + (lane & 15)) * ROWB +
                                         ks * 32 + (lane >> 4) * 16);
                uint32_t bb4[4];
                ldsm4(bb4, Bh + rb);
#pragma unroll
                for (int mi = 0; mi < 2; ++mi) {
                    mma_f32(acc[mi][2 * nt], aH[mi], bb4[0], bb4[2]);
                    mma_f32(acc[mi][2 * nt + 1], aH[mi], bb4[1], bb4[3]);
                }
#pragma unroll
                for (int mi = 0; mi < 2; ++mi) {
                    mma_f16(corr[mi][2 * nt], aL[mi], bb4[0], bb4[2]);
                    mma_f16(corr[mi][2 * nt + 1], aL[mi], bb4[1], bb4[3]);
                }
            }
        }
    };

    // prologue: 2 stages in flight
    load_chunk(0, 0);
    CP_COMMIT();
    load_chunk(1, 1);
    CP_COMMIT();
#pragma unroll 1
    for (int c = 0; c < 144; ++c) {
        int s = c % NSTAGE;
        if (c + 2 < 144) {
            CP_WAIT1();      // chunk c complete (c+1 may still be in flight)
        } else {
            CP_WAIT0();
        }
        __syncthreads();     // visibility + compute(c-1) done -> stage (c+2)%3 free
        if (c + 2 < 144) {
            load_chunk(c + 2, (c + 2) % NSTAGE);
            CP_COMMIT();
        }
        compute(s);
    }

    // merge corrections: acc += f16(corr)/512
#pragma unroll
    for (int mi = 0; mi < 2; ++mi)
#pragma unroll
        for (int j = 0; j < 8; ++j) {
            __half2 c01 = *reinterpret_cast<__half2*>(&corr[mi][j][0]);
            __half2 c23 = *reinterpret_cast<__half2*>(&corr[mi][j][1]);
            acc[mi][j][0] += __half2float(__low2half(c01)) * LO_INV;
            acc[mi][j][1] += __half2float(__high2half(c01)) * LO_INV;
            acc[mi][j][2] += __half2float(__low2half(c23)) * LO_INV;
            acc[mi][j][3] += __half2float(__high2half(c23)) * LO_INV;
        }

    // fused epilogue: h = relu(acc + b1); heatacc[p] += sum_co h * w2[co]
    float hp[2][2] = {{0.f, 0.f}, {0.f, 0.f}};
#pragma unroll
    for (int mi = 0; mi < 2; ++mi) {
#pragma unroll
        for (int nt = 0; nt < 8; ++nt) {
            int co = co0 + wn * 64 + nt * 8 + (lane & 3) * 2;
            float bv0 = b1[co], bv1 = b1[co + 1];
            float w20 = w2[co], w21 = w2[co + 1];
            float h00 = fmaxf(acc[mi][nt][0] + bv0, 0.f);
            float h01 = fmaxf(acc[mi][nt][1] + bv1, 0.f);
            float h10 = fmaxf(acc[mi][nt][2] + bv0, 0.f);
            float h11 = fmaxf(acc[mi][nt][3] + bv1, 0.f);
            hp[mi][0] += h00 * w20 + h01 * w21;
            hp[mi][1] += h10 * w20 + h11 * w21;
        }
    }
#pragma unroll
    for (int mi = 0; mi < 2; ++mi) {
        int r0 = wm * 32 + mi * 16 + (lane >> 2);
        atomicAdd(&g_heatacc[bb * HW + p0 + r0], hp[mi][0]);
        atomicAdd(&g_heatacc[bb * HW + p0 + r0 + 8], hp[mi][1]);
    }
}

// softplus(acc + b2) -> heatmap (scratch + output)
__global__ void softplus_kernel(const float* __restrict__ b2,
                                float* __restrict__ out) {
    int i = blockIdx.x * 256 + threadIdx.x;
    float a = g_heatacc[i] + b2[0];
    float sp = fmaxf(a, 0.f) + log1pf(expf(-fabsf(a)));
    g_heat[i] = sp;
    out[3 + i] = sp;
}

// per-batch: normalize to prob, add JAX (partitionable threefry) Gumbel -> score
__global__ void score_kernel() {
    __shared__ float sh[33];
    int b = blockIdx.x;
    float s = 0.f;
    for (int p = threadIdx.x; p < HW; p += 256) s += g_heat[b * HW + p];
    float S = block_sum_256(s, sh);
    for (int p = threadIdx.x; p < HW; p += 256) {
        unsigned gi = (unsigned)(b * HW + p);
        unsigned o0, o1;
        threefry2x32(0u, 42u, 0u, gi, o0, o1);
        unsigned bits = o0 ^ o1;
        float f = __uint_as_float((bits >> 9) | 0x3f800000u) - 1.0f;
        float u = fmaxf(1e-8f, f * (1.0f - 1e-8f) + 1e-8f);
        float gum = -logf(-logf(u));
        g_score[gi] = logf(g_heat[gi] / (S + 1e-6f) + 1e-12f) + gum;
    }
}

// top-256 per batch via in-smem bitonic sort
__global__ void topk_kernel() {
    __shared__ float key[HW];
    __shared__ int val[HW];
    int b = blockIdx.x;
    for (int i = threadIdx.x; i < HW; i += blockDim.x) {
        key[i] = -g_score[b * HW + i];
        val[i] = i;
    }
    for (int k = 2; k <= HW; k <<= 1)
        for (int j = k >> 1; j > 0; j >>= 1) {
            __syncthreads();
            for (int i = threadIdx.x; i < HW; i += blockDim.x) {
                int p = i ^ j;
                if (p > i) {
                    bool up = ((i & k) == 0);
                    float ki = key[i], kp = key[p];
                    if ((ki > kp) == up) {
                        key[i] = kp;
                        key[p] = ki;
                        int t = val[i];
                        val[i] = val[p];
                        val[p] = t;
                    }
                }
            }
        }
    __syncthreads();
    for (int i = threadIdx.x; i < NA; i += blockDim.x) g_idx[b * NA + i] = val[i];
}

// bilinear sample == 0.25 * sum of 4 pixels with zero pad
__global__ void gather_kernel(const float* __restrict__ T,
                              const float* __restrict__ Sf) {
    int blk = blockIdx.x;
    int b = blk >> 8, n = blk & 255;
    int idx = g_idx[b * NA + n];
    int r = idx >> 6, c = idx & 63;
    bool rv = r > 0, cv = c > 0;
    int o11 = r * WW + c, o10 = o11 - 1, o01 = o11 - WW, o00 = o01 - 1;
    for (int ch = threadIdx.x; ch < CT; ch += blockDim.x) {
        const float* base = T + (size_t)(b * CT + ch) * HW;
        float s = base[o11];
        if (cv) s += base[o10];
        if (rv) {
            s += base[o01];
            if (cv) s += base[o00];
        }
        g_sampT[(size_t)(b * NA + n) * CT + ch] = 0.25f * s;
    }
    for (int ch = threadIdx.x; ch < CS; ch += blockDim.x) {
        const float* base = Sf + (size_t)(b * CS + ch) * HW;
        float s = base[o11];
        if (cv) s += base[o10];
        if (rv) {
            s += base[o01];
            if (cv) s += base[o00];
        }
        g_sampS[(size_t)(b * NA + n) * CS + ch] = 0.25f * s;
    }
    if (threadIdx.x == 0) {
        const float* base = g_heat + b * HW;
        float s = base[o11];
        if (cv) s += base[o10];
        if (rv) {
            s += base[o01];
            if (cv) s += base[o00];
        }
        g_sal[b * NA + n] = 0.25f * s;
    }
}

// [rows,C]@[C,256] + bias -> LayerNorm -> l2norm. 8 rows per block, thread = p.
template <int C>
__global__ void proj_kernel(const float* __restrict__ wmat,
                            const float* __restrict__ bias,
                            const float* __restrict__ gamma,
                            const float* __restrict__ beta) {
    __shared__ float sRow[8 * C];
    __shared__ float sh[33];
    const float* samp = (C == CT) ? g_sampT : g_sampS;
    float* outp = (C == CT) ? g_ft : g_fs;
    int a0 = blockIdx.x * 8;
    int p = threadIdx.x;
    for (int i = threadIdx.x; i < 8 * C; i += 256) sRow[i] = samp[(size_t)a0 * C + i];
    __syncthreads();
    float acc[8];
#pragma unroll
    for (int i = 0; i < 8; ++i) acc[i] = 0.f;
    for (int c = 0; c < C; ++c) {
        float w = wmat[(size_t)c * NP + p];
#pragma unroll
        for (int i = 0; i < 8; ++i) acc[i] += sRow[i * C + c] * w;
    }
    float bi = bias[p], ga = gamma[p], be = beta[p];
#pragma unroll 1
    for (int i = 0; i < 8; ++i) {
        float x = acc[i] + bi;
        float mu = block_sum_256(x, sh) * (1.0f / NP);
        float d = x - mu;
        float var = block_sum_256(d * d, sh) * (1.0f / NP);
        float y = d * rsqrtf(var + 1e-5f) * ga + be;
        float nrm = sqrtf(block_sum_256(y * y, sh));
        y = y / fmaxf(nrm, 1e-12f);
        outp[(size_t)(a0 + i) * NP + p] = y;
    }
}

__global__ void gafd_kernel() {
    __shared__ float sh[33];
    float s = 0.f;
    const int total = NB * NA * NP;
    for (int i = blockIdx.x * blockDim.x + threadIdx.x; i < total;
         i += gridDim.x * blockDim.x) {
        float d = g_fs[i] - g_ft[i];
        s += d * d;
    }
    float bs = block_sum_256(s, sh);
    if (threadIdx.x == 0) atomicAdd(&g_gafd, bs);
}

__global__ void bd_kernel() {
    __shared__ float sh[33];
    int b = blockIdx.x;
    float s = g_sal[b * NA + threadIdx.x];
    float mx = block_max_256(s, sh);
    int bd = (s > 0.6f * mx) ? 1 : 0;
    g_bd[b * NA + threadIdx.x] = bd;
    float cnt = block_sum_256((float)bd, sh);
    if (threadIdx.x == 0) g_cnt[b] = (int)(cnt + 0.5f);
}

__global__ void abcd_kernel() {
    __shared__ float fsn[NP];
    __shared__ float sh[33];
    int blk = blockIdx.x;
    int b = blk >> 8, n = blk & 255;
    if (!g_bd[b * NA + n]) return;
    int t = threadIdx.x;
    float fv = g_fs[(size_t)(b * NA + n) * NP + t];
    float ftv = g_ft[(size_t)(b * NA + n) * NP + t];
    fsn[t] = fv;
    __syncthreads();
    float pos = block_sum_256(fv * ftv, sh) * 10.0f;  // /TAU
    const float4* fm = (const float4*)(g_fs + (size_t)(b * NA + t) * NP);
    float dm = 0.f;
#pragma unroll 4
    for (int q = 0; q < NP / 4; ++q) {
        float4 v = fm[q];
        dm += fsn[4 * q] * v.x + fsn[4 * q + 1] * v.y + fsn[4 * q + 2] * v.z +
              fsn[4 * q + 3] * v.w;
    }
    float val = g_bd[b * NA + t] ? -1e30f : dm * 10.0f;
    float mx = fmaxf(pos, block_max_256(val, sh));
    float e = (val < -1e29f) ? 0.f : expf(val - mx);
    float ssum = block_sum_256(e, sh) + expf(pos - mx);
    if (t == 0) atomicAdd(&g_abcd_b[b], mx + logf(ssum) - pos);
}

__global__ void final_kernel(float* __restrict__ out) {
    int t = threadIdx.x;
    float per = 0.f, valid = 0.f;
    if (t < NB) {
        int c = g_cnt[t];
        per = g_abcd_b[t] / fmaxf((float)c, 1.0f);
        valid = (c > 0 && c < NA) ? 1.0f : 0.0f;
    }
    float pv = per * valid;
#pragma unroll
    for (int o = 16; o; o >>= 1) {
        pv += __shfl_down_sync(0xffffffffu, pv, o);
        valid += __shfl_down_sync(0xffffffffu, valid, o);
    }
    if (t == 0) {
        float gafd = g_gafd * (1.0f / (NB * NA * NP));
        float abcd = (valid > 0.f) ? pv / valid : 0.f;
        out[0] = gafd + 0.5f * abcd;
        out[1] = gafd;
        out[2] = abcd;
    }
}

// ---------------- host launch ----------------
extern "C" void kernel_launch(void* const* d_in, const int* in_sizes, int n_in,
                              void* d_out, int out_size) {
    const float* T = (const float*)d_in[0];
    const float* Sf = (const float*)d_in[1];
    const float* w1 = (const float*)d_in[2];
    const float* b1 = (const float*)d_in[3];
    const float* w2 = (const float*)d_in[4];
    const float* b2 = (const float*)d_in[5];
    const float* tw = (const float*)d_in[6];
    const float* tb = (const float*)d_in[7];
    const float* tg = (const float*)d_in[8];
    const float* tbe = (const float*)d_in[9];
    const float* sw = (const float*)d_in[10];
    const float* sb = (const float*)d_in[11];
    const float* sg = (const float*)d_in[12];
    const float* sbe = (const float*)d_in[13];
    float* out = (float*)d_out;

    const int DSMEM = NSTAGE * STAGE_BYTES;  // 221184
    static int s_attr_done = 0;
    if (!s_attr_done) {
        cudaFuncSetAttribute(convmma_kernel,
                             cudaFuncAttributeMaxDynamicSharedMemorySize, DSMEM);
        s_attr_done = 1;
    }

    reset_kernel<<<(NB * HW + 255) / 256, 256>>>();
    tprep_kernel<<<dim3(128, 32, 16), dim3(32, 8)>>>(T);
    wprep_kernel<<<(9 * CM * CT + 255) / 256, 256>>>(w1);
    convmma_kernel<<<dim3(2, 32, 16), 512, DSMEM>>>(b1, w2);
    softplus_kernel<<<NB * HW / 256, 256>>>(b2, out);
    score_kernel<<<16, 256>>>();
    topk_kernel<<<16, 512>>>();
    gather_kernel<<<NB * NA, 256>>>(T, Sf);
    proj_kernel<CT><<<512, 256>>>(tw, tb, tg, tbe);
    proj_kernel<CS><<<512, 256>>>(sw, sb, sg, sbe);
    gafd_kernel<<<256, 256>>>();
    bd_kernel<<<NB, 256>>>();
    abcd_kernel<<<NB * NA, 256>>>();
    final_kernel<<<1, 32>>>(out);
}

// round 15
// speedup vs baseline: 2.3725x; 1.6747x over previous
#include <cuda_runtime.h>
#include <cuda_fp16.h>
#include <math.h>
#include <stdint.h>

#define NB 16
#define CT 1024
#define CS 512
#define CM 512
#define HH 64
#define WW 64
#define HW 4096
#define NP 256
#define NA 256

// ---------------- scratch (device globals; no allocation) ----------------
__device__ float g_heatacc[NB * HW];  // conv+1x1 fused accumulator
__device__ float g_heat[NB * HW];
__device__ float g_score[NB * HW];
__device__ int   g_idx[NB * NA];
__device__ float g_sampT[NB * NA * CT];
__device__ float g_sampS[NB * NA * CS];
__device__ float g_sal[NB * NA];
__device__ float g_ft[NB * NA * NP];
__device__ float g_fs[NB * NA * NP];
__device__ int   g_bd[NB * NA];
__device__ int   g_cnt[NB];
__device__ float g_gafd;
__device__ float g_abcd_b[NB];

// fp16 tensors for the conv (plain fp16-rn; error budget analyzed in journal)
__device__ __align__(16) __half g_Thi[NB * HW * CT];      // [b][p][ci]
__device__ __align__(16) __half g_Whi[9 * CM * CT];       // [tap][co][ci]

// ---------------- sm_80-class PTX helpers (compile on compute_103) --------
__device__ __forceinline__ uint32_t smem_to_u32(const void* smem_ptr) {
    uint32_t addr;
    asm("{ .reg .u64 tmp; cvta.to.shared.u64 tmp, %1; cvt.u32.u64 %0, tmp; }"
        : "=r"(addr) : "l"(smem_ptr));
    return addr;
}
__device__ __forceinline__ void cp16(uint32_t dst, const void* src, bool ok) {
    int sz = ok ? 16 : 0;
    asm volatile("cp.async.cg.shared.global [%0], [%1], 16, %2;"
                 :: "r"(dst), "l"(src), "r"(sz) : "memory");
}
#define CP_COMMIT() asm volatile("cp.async.commit_group;" ::: "memory")
#define CP_WAIT2()  asm volatile("cp.async.wait_group 2;" ::: "memory")
#define CP_WAIT1()  asm volatile("cp.async.wait_group 1;" ::: "memory")
#define CP_WAIT0()  asm volatile("cp.async.wait_group 0;" ::: "memory")

__device__ __forceinline__ void ldsm4(uint32_t* r, uint32_t addr) {
    asm volatile("ldmatrix.sync.aligned.m8n8.x4.shared.b16 {%0,%1,%2,%3}, [%4];"
                 : "=r"(r[0]), "=r"(r[1]), "=r"(r[2]), "=r"(r[3]) : "r"(addr));
}
// f32-accumulator fp16 MMA
__device__ __forceinline__ void mma_f32(float* c, const uint32_t* a,
                                        uint32_t b0, uint32_t b1) {
    asm volatile(
        "mma.sync.aligned.m16n8k16.row.col.f32.f16.f16.f32 "
        "{%0,%1,%2,%3}, {%4,%5,%6,%7}, {%8,%9}, {%0,%1,%2,%3};"
        : "+f"(c[0]), "+f"(c[1]), "+f"(c[2]), "+f"(c[3])
        : "r"(a[0]), "r"(a[1]), "r"(a[2]), "r"(a[3]), "r"(b0), "r"(b1));
}

// ---------------- generic helpers ----------------
__device__ __forceinline__ float block_sum_256(float v, float* sh) {
#pragma unroll
    for (int o = 16; o; o >>= 1) v += __shfl_down_sync(0xffffffffu, v, o);
    __syncthreads();
    if ((threadIdx.x & 31) == 0) sh[threadIdx.x >> 5] = v;
    __syncthreads();
    if (threadIdx.x == 0) {
        float t = 0.f;
        for (int i = 0; i < 8; ++i) t += sh[i];
        sh[32] = t;
    }
    __syncthreads();
    return sh[32];
}

__device__ __forceinline__ float block_max_256(float v, float* sh) {
#pragma unroll
    for (int o = 16; o; o >>= 1) v = fmaxf(v, __shfl_down_sync(0xffffffffu, v, o));
    __syncthreads();
    if ((threadIdx.x & 31) == 0) sh[threadIdx.x >> 5] = v;
    __syncthreads();
    if (threadIdx.x == 0) {
        float t = sh[0];
        for (int i = 1; i < 8; ++i) t = fmaxf(t, sh[i]);
        sh[32] = t;
    }
    __syncthreads();
    return sh[32];
}

__device__ __forceinline__ void threefry2x32(unsigned k0, unsigned k1,
                                             unsigned x0, unsigned x1,
                                             unsigned& o0, unsigned& o1) {
    unsigned ks[3] = {k0, k1, k0 ^ k1 ^ 0x1BD11BDAu};
    x0 += ks[0];
    x1 += ks[1];
    const int R[5][4] = {{13, 15, 26, 6}, {17, 29, 16, 24}, {13, 15, 26, 6},
                         {17, 29, 16, 24}, {13, 15, 26, 6}};
#pragma unroll
    for (int g = 0; g < 5; ++g) {
#pragma unroll
        for (int q = 0; q < 4; ++q) {
            x0 += x1;
            int rr = R[g][q];
            x1 = (x1 << rr) | (x1 >> (32 - rr));
            x1 ^= x0;
        }
        x0 += ks[(g + 1) % 3];
        x1 += ks[(g + 2) % 3] + (unsigned)(g + 1);
    }
    o0 = x0;
    o1 = x1;
}

// ---------------- kernels ----------------
__global__ void reset_kernel() {
    int i = blockIdx.x * blockDim.x + threadIdx.x;
    if (i < NB * HW) g_heatacc[i] = 0.f;
    if (i == 0) g_gafd = 0.f;
    if (i < NB) g_abcd_b[i] = 0.f;
}

// transpose + fp16 cast of teacher feat: T[b][ci][p] -> Thi[b][p][ci]
__global__ void tprep_kernel(const float* __restrict__ T) {
    __shared__ float tile[32][33];
    int b = blockIdx.z, p0 = blockIdx.x * 32, c0 = blockIdx.y * 32;
    int tx = threadIdx.x, ty = threadIdx.y;
    for (int i = ty; i < 32; i += 8)
        tile[i][tx] = T[((size_t)(b * CT + c0 + i)) * HW + p0 + tx];
    __syncthreads();
    for (int i = ty; i < 32; i += 8) {
        size_t o = ((size_t)b * HW + p0 + i) * CT + c0 + tx;
        g_Thi[o] = __float2half_rn(tile[tx][i]);
    }
}

// weights: W1[co][ci][tap] -> Whi[tap][co][ci] (fp16 rn)
__global__ void wprep_kernel(const float* __restrict__ W1) {
    int idx = blockIdx.x * blockDim.x + threadIdx.x;
    if (idx >= 9 * CM * CT) return;
    int ci = idx & (CT - 1);
    int rest = idx >> 10;
    int co = rest & (CM - 1);
    int tap = rest >> 9;
    g_Whi[idx] = __float2half_rn(W1[((size_t)co * CT + ci) * 9 + tap]);
}

// conv1 (pure fp16 implicit GEMM, f32 acc) fused with the 1x1 conv.
// CTA: 512 threads, 128 px x 256 co. 4-stage cp.async, 1 sync/chunk.
#define ROWB 144                      // bytes per smem row (64 fp16 + 8 pad)
#define A_BYTES (128 * ROWB)          // 18432
#define B_BYTES (256 * ROWB)          // 36864
#define STAGE_BYTES (A_BYTES + B_BYTES)  // 55296
#define NSTAGE 4
__global__ __launch_bounds__(512, 1)
void convmma_kernel(const float* __restrict__ b1, const float* __restrict__ w2) {
    extern __shared__ char dsm[];
    uint32_t sb = smem_to_u32(dsm);
    int tid = threadIdx.x, lane = tid & 31, wid = tid >> 5;
    int co0 = blockIdx.x * 256;
    int pixtile = blockIdx.y;
    int bb = blockIdx.z;
    int y0 = pixtile * 2, p0 = pixtile * 128;
    int wm = wid & 3, wn = wid >> 2;   // 4 M-groups of 32 px; 4 N-groups of 64 co

    float acc[2][8][4];
#pragma unroll
    for (int i = 0; i < 2; ++i)
#pragma unroll
        for (int j = 0; j < 8; ++j)
#pragma unroll
            for (int k = 0; k < 4; ++k) acc[i][j][k] = 0.f;

    auto load_chunk = [&](int c, int s) {
        int tap = c >> 4, kc = c & 15;
        int dy = tap / 3 - 1, dx = tap % 3 - 1;
        int ci0 = kc * 64;
        uint32_t base = sb + (uint32_t)s * STAGE_BYTES;
        // A: 128 pixel rows x 64 ci, shifted + zero-masked
#pragma unroll
        for (int i = 0; i < 2; ++i) {
            int u = i * 512 + tid;
            int r = u >> 3, seg = u & 7;
            int ys = y0 + (r >> 6) + dy;
            int xs = (r & 63) + dx;
            bool ok = ((unsigned)ys < 64u) && ((unsigned)xs < 64u);
            int ysc = ok ? ys : 0, xsc = ok ? xs : 0;
            size_t g = ((size_t)(bb * HW + ysc * 64 + xsc)) * CT + ci0 + seg * 8;
            uint32_t off = (uint32_t)(r * ROWB + seg * 16);
            cp16(base + off, g_Thi + g, ok);
        }
        // B: 256 co rows x 64 ci
#pragma unroll
        for (int i = 0; i < 4; ++i) {
            int u = i * 512 + tid;
            int r = u >> 3, seg = u & 7;
            size_t g = ((size_t)(tap * CM + co0 + r)) * CT + ci0 + seg * 8;
            uint32_t off = (uint32_t)(r * ROWB + seg * 16);
            cp16(base + A_BYTES + off, g_Whi + g, true);
        }
    };

    auto compute = [&](int s) {
        uint32_t Ah = sb + (uint32_t)s * STAGE_BYTES;
        uint32_t Bh = Ah + A_BYTES;
#pragma unroll
        for (int ks = 0; ks < 4; ++ks) {
            uint32_t aH[2][4];
#pragma unroll
            for (int t = 0; t < 2; ++t) {
                uint32_t ra = (uint32_t)((wm * 32 + t * 16 + (lane & 15)) * ROWB +
                                         ks * 32 + (lane >> 4) * 16);
                ldsm4(aH[t], Ah + ra);
            }
#pragma unroll
            for (int nt = 0; nt < 4; ++nt) {
                uint32_t rb = (uint32_t)((wn * 64 + nt * 16 + (lane & 15)) * ROWB +
                                         ks * 32 + (lane >> 4) * 16);
                uint32_t bb4[4];
                ldsm4(bb4, Bh + rb);
#pragma unroll
                for (int mi = 0; mi < 2; ++mi) {
                    mma_f32(acc[mi][2 * nt], aH[mi], bb4[0], bb4[2]);
                    mma_f32(acc[mi][2 * nt + 1], aH[mi], bb4[1], bb4[3]);
                }
            }
        }
    };

    // prologue: 3 stages in flight
    load_chunk(0, 0);
    CP_COMMIT();
    load_chunk(1, 1);
    CP_COMMIT();
    load_chunk(2, 2);
    CP_COMMIT();
#pragma unroll 1
    for (int c = 0; c < 144; ++c) {
        int s = c & 3;
        if (c < 142) CP_WAIT2();
        else if (c == 142) CP_WAIT1();
        else CP_WAIT0();
        __syncthreads();     // visibility + compute(c-1) done -> stage (c+3)&3 free
        if (c + 3 < 144) {
            load_chunk(c + 3, (c + 3) & 3);
            CP_COMMIT();
        }
        compute(s);
    }

    // fused epilogue: h = relu(acc + b1); heatacc[p] += sum_co h * w2[co]
    float hp[2][2] = {{0.f, 0.f}, {0.f, 0.f}};
#pragma unroll
    for (int mi = 0; mi < 2; ++mi) {
#pragma unroll
        for (int nt = 0; nt < 8; ++nt) {
            int co = co0 + wn * 64 + nt * 8 + (lane & 3) * 2;
            float bv0 = b1[co], bv1 = b1[co + 1];
            float w20 = w2[co], w21 = w2[co + 1];
            float h00 = fmaxf(acc[mi][nt][0] + bv0, 0.f);
            float h01 = fmaxf(acc[mi][nt][1] + bv1, 0.f);
            float h10 = fmaxf(acc[mi][nt][2] + bv0, 0.f);
            float h11 = fmaxf(acc[mi][nt][3] + bv1, 0.f);
            hp[mi][0] += h00 * w20 + h01 * w21;
            hp[mi][1] += h10 * w20 + h11 * w21;
        }
    }
#pragma unroll
    for (int mi = 0; mi < 2; ++mi) {
        int r0 = wm * 32 + mi * 16 + (lane >> 2);
        atomicAdd(&g_heatacc[bb * HW + p0 + r0], hp[mi][0]);
        atomicAdd(&g_heatacc[bb * HW + p0 + r0 + 8], hp[mi][1]);
    }
}

// softplus(acc + b2) -> heatmap (scratch + output)
__global__ void softplus_kernel(const float* __restrict__ b2,
                                float* __restrict__ out) {
    int i = blockIdx.x * 256 + threadIdx.x;
    float a = g_heatacc[i] + b2[0];
    float sp = fmaxf(a, 0.f) + log1pf(expf(-fabsf(a)));
    g_heat[i] = sp;
    out[3 + i] = sp;
}

// per-batch: normalize to prob, add JAX (partitionable threefry) Gumbel -> score
__global__ void score_kernel() {
    __shared__ float sh[33];
    int b = blockIdx.x;
    float s = 0.f;
    for (int p = threadIdx.x; p < HW; p += 256) s += g_heat[b * HW + p];
    float S = block_sum_256(s, sh);
    for (int p = threadIdx.x; p < HW; p += 256) {
        unsigned gi = (unsigned)(b * HW + p);
        unsigned o0, o1;
        threefry2x32(0u, 42u, 0u, gi, o0, o1);
        unsigned bits = o0 ^ o1;
        float f = __uint_as_float((bits >> 9) | 0x3f800000u) - 1.0f;
        float u = fmaxf(1e-8f, f * (1.0f - 1e-8f) + 1e-8f);
        float gum = -logf(-logf(u));
        g_score[gi] = logf(g_heat[gi] / (S + 1e-6f) + 1e-12f) + gum;
    }
}

// top-256 per batch via in-smem bitonic sort
__global__ void topk_kernel() {
    __shared__ float key[HW];
    __shared__ int val[HW];
    int b = blockIdx.x;
    for (int i = threadIdx.x; i < HW; i += blockDim.x) {
        key[i] = -g_score[b * HW + i];
        val[i] = i;
    }
    for (int k = 2; k <= HW; k <<= 1)
        for (int j = k >> 1; j > 0; j >>= 1) {
            __syncthreads();
            for (int i = threadIdx.x; i < HW; i += blockDim.x) {
                int p = i ^ j;
                if (p > i) {
                    bool up = ((i & k) == 0);
                    float ki = key[i], kp = key[p];
                    if ((ki > kp) == up) {
                        key[i] = kp;
                        key[p] = ki;
                        int t = val[i];
                        val[i] = val[p];
                        val[p] = t;
                    }
                }
            }
        }
    __syncthreads();
    for (int i = threadIdx.x; i < NA; i += blockDim.x) g_idx[b * NA + i] = val[i];
}

// bilinear sample == 0.25 * sum of 4 pixels with zero pad
__global__ void gather_kernel(const float* __restrict__ T,
                              const float* __restrict__ Sf) {
    int blk = blockIdx.x;
    int b = blk >> 8, n = blk & 255;
    int idx = g_idx[b * NA + n];
    int r = idx >> 6, c = idx & 63;
    bool rv = r > 0, cv = c > 0;
    int o11 = r * WW + c, o10 = o11 - 1, o01 = o11 - WW, o00 = o01 - 1;
    for (int ch = threadIdx.x; ch < CT; ch += blockDim.x) {
        const float* base = T + (size_t)(b * CT + ch) * HW;
        float s = base[o11];
        if (cv) s += base[o10];
        if (rv) {
            s += base[o01];
            if (cv) s += base[o00];
        }
        g_sampT[(size_t)(b * NA + n) * CT + ch] = 0.25f * s;
    }
    for (int ch = threadIdx.x; ch < CS; ch += blockDim.x) {
        const float* base = Sf + (size_t)(b * CS + ch) * HW;
        float s = base[o11];
        if (cv) s += base[o10];
        if (rv) {
            s += base[o01];
            if (cv) s += base[o00];
        }
        g_sampS[(size_t)(b * NA + n) * CS + ch] = 0.25f * s;
    }
    if (threadIdx.x == 0) {
        const float* base = g_heat + b * HW;
        float s = base[o11];
        if (cv) s += base[o10];
        if (rv) {
            s += base[o01];
            if (cv) s += base[o00];
        }
        g_sal[b * NA + n] = 0.25f * s;
    }
}

// [rows,C]@[C,256] + bias -> LayerNorm -> l2norm. 8 rows per block, thread = p.
template <int C>
__global__ void proj_kernel(const float* __restrict__ wmat,
                            const float* __restrict__ bias,
                            const float* __restrict__ gamma,
                            const float* __restrict__ beta) {
    __shared__ float sRow[8 * C];
    __shared__ float sh[33];
    const float* samp = (C == CT) ? g_sampT : g_sampS;
    float* outp = (C == CT) ? g_ft : g_fs;
    int a0 = blockIdx.x * 8;
    int p = threadIdx.x;
    for (int i = threadIdx.x; i < 8 * C; i += 256) sRow[i] = samp[(size_t)a0 * C + i];
    __syncthreads();
    float acc[8];
#pragma unroll
    for (int i = 0; i < 8; ++i) acc[i] = 0.f;
    for (int c = 0; c < C; ++c) {
        float w = wmat[(size_t)c * NP + p];
#pragma unroll
        for (int i = 0; i < 8; ++i) acc[i] += sRow[i * C + c] * w;
    }
    float bi = bias[p], ga = gamma[p], be = beta[p];
#pragma unroll 1
    for (int i = 0; i < 8; ++i) {
        float x = acc[i] + bi;
        float mu = block_sum_256(x, sh) * (1.0f / NP);
        float d = x - mu;
        float var = block_sum_256(d * d, sh) * (1.0f / NP);
        float y = d * rsqrtf(var + 1e-5f) * ga + be;
        float nrm = sqrtf(block_sum_256(y * y, sh));
        y = y / fmaxf(nrm, 1e-12f);
        outp[(size_t)(a0 + i) * NP + p] = y;
    }
}

__global__ void gafd_kernel() {
    __shared__ float sh[33];
    float s = 0.f;
    const int total = NB * NA * NP;
    for (int i = blockIdx.x * blockDim.x + threadIdx.x; i < total;
         i += gridDim.x * blockDim.x) {
        float d = g_fs[i] - g_ft[i];
        s += d * d;
    }
    float bs = block_sum_256(s, sh);
    if (threadIdx.x == 0) atomicAdd(&g_gafd, bs);
}

__global__ void bd_kernel() {
    __shared__ float sh[33];
    int b = blockIdx.x;
    float s = g_sal[b * NA + threadIdx.x];
    float mx = block_max_256(s, sh);
    int bd = (s > 0.6f * mx) ? 1 : 0;
    g_bd[b * NA + threadIdx.x] = bd;
    float cnt = block_sum_256((float)bd, sh);
    if (threadIdx.x == 0) g_cnt[b] = (int)(cnt + 0.5f);
}

__global__ void abcd_kernel() {
    __shared__ float fsn[NP];
    __shared__ float sh[33];
    int blk = blockIdx.x;
    int b = blk >> 8, n = blk & 255;
    if (!g_bd[b * NA + n]) return;
    int t = threadIdx.x;
    float fv = g_fs[(size_t)(b * NA + n) * NP + t];
    float ftv = g_ft[(size_t)(b * NA + n) * NP + t];
    fsn[t] = fv;
    __syncthreads();
    float pos = block_sum_256(fv * ftv, sh) * 10.0f;  // /TAU
    const float4* fm = (const float4*)(g_fs + (size_t)(b * NA + t) * NP);
    float dm = 0.f;
#pragma unroll 4
    for (int q = 0; q < NP / 4; ++q) {
        float4 v = fm[q];
        dm += fsn[4 * q] * v.x + fsn[4 * q + 1] * v.y + fsn[4 * q + 2] * v.z +
              fsn[4 * q + 3] * v.w;
    }
    float val = g_bd[b * NA + t] ? -1e30f : dm * 10.0f;
    float mx = fmaxf(pos, block_max_256(val, sh));
    float e = (val < -1e29f) ? 0.f : expf(val - mx);
    float ssum = block_sum_256(e, sh) + expf(pos - mx);
    if (t == 0) atomicAdd(&g_abcd_b[b], mx + logf(ssum) - pos);
}

__global__ void final_kernel(float* __restrict__ out) {
    int t = threadIdx.x;
    float per = 0.f, valid = 0.f;
    if (t < NB) {
        int c = g_cnt[t];
        per = g_abcd_b[t] / fmaxf((float)c, 1.0f);
        valid = (c > 0 && c < NA) ? 1.0f : 0.0f;
    }
    float pv = per * valid;
#pragma unroll
    for (int o = 16; o; o >>= 1) {
        pv += __shfl_down_sync(0xffffffffu, pv, o);
        valid += __shfl_down_sync(0xffffffffu, valid, o);
    }
    if (t == 0) {
        float gafd = g_gafd * (1.0f / (NB * NA * NP));
        float abcd = (valid > 0.f) ? pv / valid : 0.f;
        out[0] = gafd + 0.5f * abcd;
        out[1] = gafd;
        out[2] = abcd;
    }
}

// ---------------- host launch ----------------
extern "C" void kernel_launch(void* const* d_in, const int* in_sizes, int n_in,
                              void* d_out, int out_size) {
    const float* T = (const float*)d_in[0];
    const float* Sf = (const float*)d_in[1];
    const float* w1 = (const float*)d_in[2];
    const float* b1 = (const float*)d_in[3];
    const float* w2 = (const float*)d_in[4];
    const float* b2 = (const float*)d_in[5];
    const float* tw = (const float*)d_in[6];
    const float* tb = (const float*)d_in[7];
    const float* tg = (const float*)d_in[8];
    const float* tbe = (const float*)d_in[9];
    const float* sw = (const float*)d_in[10];
    const float* sb = (const float*)d_in[11];
    const float* sg = (const float*)d_in[12];
    const float* sbe = (const float*)d_in[13];
    float* out = (float*)d_out;

    const int DSMEM = NSTAGE * STAGE_BYTES;  // 221184
    static int s_attr_done = 0;
    if (!s_attr_done) {
        cudaFuncSetAttribute(convmma_kernel,
                             cudaFuncAttributeMaxDynamicSharedMemorySize, DSMEM);
        s_attr_done = 1;
    }

    reset_kernel<<<(NB * HW + 255) / 256, 256>>>();
    tprep_kernel<<<dim3(128, 32, 16), dim3(32, 8)>>>(T);
    wprep_kernel<<<(9 * CM * CT + 255) / 256, 256>>>(w1);
    convmma_kernel<<<dim3(2, 32, 16), 512, DSMEM>>>(b1, w2);
    softplus_kernel<<<NB * HW / 256, 256>>>(b2, out);
    score_kernel<<<16, 256>>>();
    topk_kernel<<<16, 512>>>();
    gather_kernel<<<NB * NA, 256>>>(T, Sf);
    proj_kernel<CT><<<512, 256>>>(tw, tb, tg, tbe);
    proj_kernel<CS><<<512, 256>>>(sw, sb, sg, sbe);
    gafd_kernel<<<256, 256>>>();
    bd_kernel<<<NB, 256>>>();
    abcd_kernel<<<NB * NA, 256>>>();
    final_kernel<<<1, 32>>>(out);
}

// round 16
// speedup vs baseline: 2.4552x; 1.0348x over previous
#include <cuda_runtime.h>
#include <cuda_fp16.h>
#include <math.h>
#include <stdint.h>

#define NB 16
#define CT 1024
#define CS 512
#define CM 512
#define HH 64
#define WW 64
#define HW 4096
#define NP 256
#define NA 256

// ---------------- scratch (device globals; no allocation) ----------------
__device__ float g_heatacc[NB * HW];  // conv+1x1 fused accumulator
__device__ float g_heat[NB * HW];
__device__ float g_score[NB * HW];
__device__ int   g_idx[NB * NA];
__device__ float g_sampT[NB * NA * CT];
__device__ float g_sampS[NB * NA * CS];
__device__ float g_sal[NB * NA];
__device__ float g_ft[NB * NA * NP];
__device__ float g_fs[NB * NA * NP];
__device__ int   g_bd[NB * NA];
__device__ int   g_cnt[NB];
__device__ float g_gafd;
__device__ float g_abcd_b[NB];

// fp16 tensors for the conv
__device__ __align__(16) __half g_Thi[NB * HW * CT];      // [b][p][ci]
__device__ __align__(16) __half g_Whi[9 * CM * CT];       // [tap][co][ci]

// ---------------- sm_80-class PTX helpers (compile on compute_103) --------
__device__ __forceinline__ uint32_t smem_to_u32(const void* smem_ptr) {
    uint32_t addr;
    asm("{ .reg .u64 tmp; cvta.to.shared.u64 tmp, %1; cvt.u32.u64 %0, tmp; }"
        : "=r"(addr) : "l"(smem_ptr));
    return addr;
}
__device__ __forceinline__ void cp16(uint32_t dst, const void* src, bool ok) {
    int sz = ok ? 16 : 0;
    asm volatile("cp.async.cg.shared.global [%0], [%1], 16, %2;"
                 :: "r"(dst), "l"(src), "r"(sz) : "memory");
}
#define CP_COMMIT() asm volatile("cp.async.commit_group;" ::: "memory")
#define CP_WAIT1()  asm volatile("cp.async.wait_group 1;" ::: "memory")
#define CP_WAIT0()  asm volatile("cp.async.wait_group 0;" ::: "memory")

__device__ __forceinline__ void ldsm4(uint32_t* r, uint32_t addr) {
    asm volatile("ldmatrix.sync.aligned.m8n8.x4.shared.b16 {%0,%1,%2,%3}, [%4];"
                 : "=r"(r[0]), "=r"(r[1]), "=r"(r[2]), "=r"(r[3]) : "r"(addr));
}
// f32-accumulator fp16 MMA
__device__ __forceinline__ void mma_f32(float* c, const uint32_t* a,
                                        uint32_t b0, uint32_t b1) {
    asm volatile(
        "mma.sync.aligned.m16n8k16.row.col.f32.f16.f16.f32 "
        "{%0,%1,%2,%3}, {%4,%5,%6,%7}, {%8,%9}, {%0,%1,%2,%3};"
        : "+f"(c[0]), "+f"(c[1]), "+f"(c[2]), "+f"(c[3])
        : "r"(a[0]), "r"(a[1]), "r"(a[2]), "r"(a[3]), "r"(b0), "r"(b1));
}

// ---------------- generic helpers ----------------
__device__ __forceinline__ float block_sum_256(float v, float* sh) {
#pragma unroll
    for (int o = 16; o; o >>= 1) v += __shfl_down_sync(0xffffffffu, v, o);
    __syncthreads();
    if ((threadIdx.x & 31) == 0) sh[threadIdx.x >> 5] = v;
    __syncthreads();
    if (threadIdx.x == 0) {
        float t = 0.f;
        for (int i = 0; i < 8; ++i) t += sh[i];
        sh[32] = t;
    }
    __syncthreads();
    return sh[32];
}

__device__ __forceinline__ float block_max_256(float v, float* sh) {
#pragma unroll
    for (int o = 16; o; o >>= 1) v = fmaxf(v, __shfl_down_sync(0xffffffffu, v, o));
    __syncthreads();
    if ((threadIdx.x & 31) == 0) sh[threadIdx.x >> 5] = v;
    __syncthreads();
    if (threadIdx.x == 0) {
        float t = sh[0];
        for (int i = 1; i < 8; ++i) t = fmaxf(t, sh[i]);
        sh[32] = t;
    }
    __syncthreads();
    return sh[32];
}

__device__ __forceinline__ void threefry2x32(unsigned k0, unsigned k1,
                                             unsigned x0, unsigned x1,
                                             unsigned& o0, unsigned& o1) {
    unsigned ks[3] = {k0, k1, k0 ^ k1 ^ 0x1BD11BDAu};
    x0 += ks[0];
    x1 += ks[1];
    const int R[5][4] = {{13, 15, 26, 6}, {17, 29, 16, 24}, {13, 15, 26, 6},
                         {17, 29, 16, 24}, {13, 15, 26, 6}};
#pragma unroll
    for (int g = 0; g < 5; ++g) {
#pragma unroll
        for (int q = 0; q < 4; ++q) {
            x0 += x1;
            int rr = R[g][q];
            x1 = (x1 << rr) | (x1 >> (32 - rr));
            x1 ^= x0;
        }
        x0 += ks[(g + 1) % 3];
        x1 += ks[(g + 2) % 3] + (unsigned)(g + 1);
    }
    o0 = x0;
    o1 = x1;
}

// ---------------- kernels ----------------
__global__ void reset_kernel() {
    int i = blockIdx.x * blockDim.x + threadIdx.x;
    if (i < NB * HW) g_heatacc[i] = 0.f;
    if (i == 0) g_gafd = 0.f;
    if (i < NB) g_abcd_b[i] = 0.f;
}

// transpose + fp16 cast of teacher feat: T[b][ci][p] -> Thi[b][p][ci]
__global__ void tprep_kernel(const float* __restrict__ T) {
    __shared__ float tile[32][33];
    int b = blockIdx.z, p0 = blockIdx.x * 32, c0 = blockIdx.y * 32;
    int tx = threadIdx.x, ty = threadIdx.y;
    for (int i = ty; i < 32; i += 8)
        tile[i][tx] = T[((size_t)(b * CT + c0 + i)) * HW + p0 + tx];
    __syncthreads();
    for (int i = ty; i < 32; i += 8) {
        size_t o = ((size_t)b * HW + p0 + i) * CT + c0 + tx;
        g_Thi[o] = __float2half_rn(tile[tx][i]);
    }
}

// weights: W1[co][ci][tap] -> Whi[tap][co][ci] (fp16 rn)
__global__ void wprep_kernel(const float* __restrict__ W1) {
    int idx = blockIdx.x * blockDim.x + threadIdx.x;
    if (idx >= 9 * CM * CT) return;
    int ci = idx & (CT - 1);
    int rest = idx >> 10;
    int co = rest & (CM - 1);
    int tap = rest >> 9;
    g_Whi[idx] = __float2half_rn(W1[((size_t)co * CT + ci) * 9 + tap]);
}

// conv1 (pure fp16 implicit GEMM, f32 acc) fused with the 1x1 conv.
// CTA: 256 threads, 128 px x 128 co; 3-stage cp.async, single sync/chunk,
// 2 CTAs per SM (anti-phased), hoisted u32 address bases.
#define ROWB 144                      // bytes per smem row (64 fp16 + 8 pad)
#define AT_BYTES (128 * ROWB)         // 18432
#define STG (2 * AT_BYTES)            // A + B = 36864
#define NST 3
__global__ __launch_bounds__(256, 2)
void convmma_kernel(const float* __restrict__ b1, const float* __restrict__ w2) {
    extern __shared__ char dsm[];
    uint32_t sb = smem_to_u32(dsm);
    int tid = threadIdx.x, lane = tid & 31, wid = tid >> 5;
    int co0 = blockIdx.x * 128;
    int pixtile = blockIdx.y;
    int bb = blockIdx.z;
    int y0 = pixtile * 2, p0 = pixtile * 128;
    int wm = wid & 3, wn = wid >> 2;   // 4 M-groups of 32 px; 2 N-groups of 64 co

    float acc[2][8][4];
#pragma unroll
    for (int i = 0; i < 2; ++i)
#pragma unroll
        for (int j = 0; j < 8; ++j)
#pragma unroll
            for (int k = 0; k < 4; ++k) acc[i][j][k] = 0.f;

    // hoisted per-thread load state (u32 element bases)
    uint32_t aoff[4], agbase[4], bgbase[4];
    int ays[4], axs[4];
#pragma unroll
    for (int i = 0; i < 4; ++i) {
        int u = i * 256 + tid;
        int r = u >> 3, seg = u & 7;
        int ys0 = y0 + (r >> 6), xs0 = r & 63;
        ays[i] = ys0;
        axs[i] = xs0;
        agbase[i] = (uint32_t)((bb * HW + ys0 * 64 + xs0) * CT + seg * 8);
        aoff[i] = (uint32_t)(r * ROWB + seg * 16);
        bgbase[i] = (uint32_t)((co0 + r) * CT + seg * 8);
    }

    auto load_chunk = [&](int c, int s) {
        int tap = c >> 4, kc = c & 15;
        int dy = tap / 3 - 1, dx = tap % 3 - 1;
        uint32_t ci0 = (uint32_t)(kc * 64);
        uint32_t deltaA = (uint32_t)((dy * 64 + dx) * CT) + ci0;  // mod-2^32 ok
        uint32_t deltaB = (uint32_t)(tap * CM * CT) + ci0;
        uint32_t base = sb + (uint32_t)s * STG;
#pragma unroll
        for (int i = 0; i < 4; ++i) {
            bool ok = ((unsigned)(ays[i] + dy) < 64u) &&
                      ((unsigned)(axs[i] + dx) < 64u);
            uint32_t d = ok ? deltaA : ci0;  // !ok: valid fallback addr, sz=0
            cp16(base + aoff[i], g_Thi + (agbase[i] + d), ok);
        }
#pragma unroll
        for (int i = 0; i < 4; ++i)
            cp16(base + AT_BYTES + aoff[i], g_Whi + (bgbase[i] + deltaB), true);
    };

    auto compute = [&](int s) {
        uint32_t Ah = sb + (uint32_t)s * STG;
        uint32_t Bh = Ah + AT_BYTES;
#pragma unroll
        for (int ks = 0; ks < 4; ++ks) {
            uint32_t aH[2][4];
#pragma unroll
            for (int t = 0; t < 2; ++t) {
                uint32_t ra = (uint32_t)((wm * 32 + t * 16 + (lane & 15)) * ROWB +
                                         ks * 32 + (lane >> 4) * 16);
                ldsm4(aH[t], Ah + ra);
            }
#pragma unroll
            for (int nt = 0; nt < 4; ++nt) {
                uint32_t rb = (uint32_t)((wn * 64 + nt * 16 + (lane & 15)) * ROWB +
                                         ks * 32 + (lane >> 4) * 16);
                uint32_t bb4[4];
                ldsm4(bb4, Bh + rb);
#pragma unroll
                for (int mi = 0; mi < 2; ++mi) {
                    mma_f32(acc[mi][2 * nt], aH[mi], bb4[0], bb4[2]);
                    mma_f32(acc[mi][2 * nt + 1], aH[mi], bb4[1], bb4[3]);
                }
            }
        }
    };

    // prologue: 2 stages in flight
    load_chunk(0, 0);
    CP_COMMIT();
    load_chunk(1, 1);
    CP_COMMIT();
#pragma unroll 1
    for (int c = 0; c < 144; ++c) {
        int s = c % NST;
        if (c + 2 < 144) CP_WAIT1();
        else CP_WAIT0();
        __syncthreads();     // chunk c visible + compute(c-1) done -> stage free
        if (c + 2 < 144) {
            load_chunk(c + 2, (c + 2) % NST);
            CP_COMMIT();
        }
        compute(s);
    }

    // fused epilogue: h = relu(acc + b1); heatacc[p] += sum_co h * w2[co]
    float hp[2][2] = {{0.f, 0.f}, {0.f, 0.f}};
#pragma unroll
    for (int mi = 0; mi < 2; ++mi) {
#pragma unroll
        for (int nt = 0; nt < 8; ++nt) {
            int co = co0 + wn * 64 + nt * 8 + (lane & 3) * 2;
            float bv0 = b1[co], bv1 = b1[co + 1];
            float w20 = w2[co], w21 = w2[co + 1];
            float h00 = fmaxf(acc[mi][nt][0] + bv0, 0.f);
            float h01 = fmaxf(acc[mi][nt][1] + bv1, 0.f);
            float h10 = fmaxf(acc[mi][nt][2] + bv0, 0.f);
            float h11 = fmaxf(acc[mi][nt][3] + bv1, 0.f);
            hp[mi][0] += h00 * w20 + h01 * w21;
            hp[mi][1] += h10 * w20 + h11 * w21;
        }
    }
#pragma unroll
    for (int mi = 0; mi < 2; ++mi) {
        int r0 = wm * 32 + mi * 16 + (lane >> 2);
        atomicAdd(&g_heatacc[bb * HW + p0 + r0], hp[mi][0]);
        atomicAdd(&g_heatacc[bb * HW + p0 + r0 + 8], hp[mi][1]);
    }
}

// softplus(acc + b2) -> heatmap (scratch + output)
__global__ void softplus_kernel(const float* __restrict__ b2,
                                float* __restrict__ out) {
    int i = blockIdx.x * 256 + threadIdx.x;
    float a = g_heatacc[i] + b2[0];
    float sp = fmaxf(a, 0.f) + log1pf(expf(-fabsf(a)));
    g_heat[i] = sp;
    out[3 + i] = sp;
}

// per-batch: normalize to prob, add JAX (partitionable threefry) Gumbel -> score
__global__ void score_kernel() {
    __shared__ float sh[33];
    int b = blockIdx.x;
    float s = 0.f;
    for (int p = threadIdx.x; p < HW; p += 256) s += g_heat[b * HW + p];
    float S = block_sum_256(s, sh);
    for (int p = threadIdx.x; p < HW; p += 256) {
        unsigned gi = (unsigned)(b * HW + p);
        unsigned o0, o1;
        threefry2x32(0u, 42u, 0u, gi, o0, o1);
        unsigned bits = o0 ^ o1;
        float f = __uint_as_float((bits >> 9) | 0x3f800000u) - 1.0f;
        float u = fmaxf(1e-8f, f * (1.0f - 1e-8f) + 1e-8f);
        float gum = -logf(-logf(u));
        g_score[gi] = logf(g_heat[gi] / (S + 1e-6f) + 1e-12f) + gum;
    }
}

// top-256 per batch via in-smem bitonic sort
__global__ void topk_kernel() {
    __shared__ float key[HW];
    __shared__ int val[HW];
    int b = blockIdx.x;
    for (int i = threadIdx.x; i < HW; i += blockDim.x) {
        key[i] = -g_score[b * HW + i];
        val[i] = i;
    }
    for (int k = 2; k <= HW; k <<= 1)
        for (int j = k >> 1; j > 0; j >>= 1) {
            __syncthreads();
            for (int i = threadIdx.x; i < HW; i += blockDim.x) {
                int p = i ^ j;
                if (p > i) {
                    bool up = ((i & k) == 0);
                    float ki = key[i], kp = key[p];
                    if ((ki > kp) == up) {
                        key[i] = kp;
                        key[p] = ki;
                        int t = val[i];
                        val[i] = val[p];
                        val[p] = t;
                    }
                }
            }
        }
    __syncthreads();
    for (int i = threadIdx.x; i < NA; i += blockDim.x) g_idx[b * NA + i] = val[i];
}

// bilinear sample == 0.25 * sum of 4 pixels with zero pad
__global__ void gather_kernel(const float* __restrict__ T,
                              const float* __restrict__ Sf) {
    int blk = blockIdx.x;
    int b = blk >> 8, n = blk & 255;
    int idx = g_idx[b * NA + n];
    int r = idx >> 6, c = idx & 63;
    bool rv = r > 0, cv = c > 0;
    int o11 = r * WW + c, o10 = o11 - 1, o01 = o11 - WW, o00 = o01 - 1;
    for (int ch = threadIdx.x; ch < CT; ch += blockDim.x) {
        const float* base = T + (size_t)(b * CT + ch) * HW;
        float s = base[o11];
        if (cv) s += base[o10];
        if (rv) {
            s += base[o01];
            if (cv) s += base[o00];
        }
        g_sampT[(size_t)(b * NA + n) * CT + ch] = 0.25f * s;
    }
    for (int ch = threadIdx.x; ch < CS; ch += blockDim.x) {
        const float* base = Sf + (size_t)(b * CS + ch) * HW;
        float s = base[o11];
        if (cv) s += base[o10];
        if (rv) {
            s += base[o01];
            if (cv) s += base[o00];
        }
        g_sampS[(size_t)(b * NA + n) * CS + ch] = 0.25f * s;
    }
    if (threadIdx.x == 0) {
        const float* base = g_heat + b * HW;
        float s = base[o11];
        if (cv) s += base[o10];
        if (rv) {
            s += base[o01];
            if (cv) s += base[o00];
        }
        g_sal[b * NA + n] = 0.25f * s;
    }
}

// [rows,C]@[C,256] + bias -> LayerNorm -> l2norm. 8 rows per block, thread = p.
template <int C>
__global__ void proj_kernel(const float* __restrict__ wmat,
                            const float* __restrict__ bias,
                            const float* __restrict__ gamma,
                            const float* __restrict__ beta) {
    __shared__ float sRow[8 * C];
    __shared__ float sh[33];
    const float* samp = (C == CT) ? g_sampT : g_sampS;
    float* outp = (C == CT) ? g_ft : g_fs;
    int a0 = blockIdx.x * 8;
    int p = threadIdx.x;
    for (int i = threadIdx.x; i < 8 * C; i += 256) sRow[i] = samp[(size_t)a0 * C + i];
    __syncthreads();
    float acc[8];
#pragma unroll
    for (int i = 0; i < 8; ++i) acc[i] = 0.f;
    for (int c = 0; c < C; ++c) {
        float w = wmat[(size_t)c * NP + p];
#pragma unroll
        for (int i = 0; i < 8; ++i) acc[i] += sRow[i * C + c] * w;
    }
    float bi = bias[p], ga = gamma[p], be = beta[p];
#pragma unroll 1
    for (int i = 0; i < 8; ++i) {
        float x = acc[i] + bi;
        float mu = block_sum_256(x, sh) * (1.0f / NP);
        float d = x - mu;
        float var = block_sum_256(d * d, sh) * (1.0f / NP);
        float y = d * rsqrtf(var + 1e-5f) * ga + be;
        float nrm = sqrtf(block_sum_256(y * y, sh));
        y = y / fmaxf(nrm, 1e-12f);
        outp[(size_t)(a0 + i) * NP + p] = y;
    }
}

__global__ void gafd_kernel() {
    __shared__ float sh[33];
    float s = 0.f;
    const int total = NB * NA * NP;
    for (int i = blockIdx.x * blockDim.x + threadIdx.x; i < total;
         i += gridDim.x * blockDim.x) {
        float d = g_fs[i] - g_ft[i];
        s += d * d;
    }
    float bs = block_sum_256(s, sh);
    if (threadIdx.x == 0) atomicAdd(&g_gafd, bs);
}

__global__ void bd_kernel() {
    __shared__ float sh[33];
    int b = blockIdx.x;
    float s = g_sal[b * NA + threadIdx.x];
    float mx = block_max_256(s, sh);
    int bd = (s > 0.6f * mx) ? 1 : 0;
    g_bd[b * NA + threadIdx.x] = bd;
    float cnt = block_sum_256((float)bd, sh);
    if (threadIdx.x == 0) g_cnt[b] = (int)(cnt + 0.5f);
}

__global__ void abcd_kernel() {
    __shared__ float fsn[NP];
    __shared__ float sh[33];
    int blk = blockIdx.x;
    int b = blk >> 8, n = blk & 255;
    if (!g_bd[b * NA + n]) return;
    int t = threadIdx.x;
    float fv = g_fs[(size_t)(b * NA + n) * NP + t];
    float ftv = g_ft[(size_t)(b * NA + n) * NP + t];
    fsn[t] = fv;
    __syncthreads();
    float pos = block_sum_256(fv * ftv, sh) * 10.0f;  // /TAU
    const float4* fm = (const float4*)(g_fs + (size_t)(b * NA + t) * NP);
    float dm = 0.f;
#pragma unroll 4
    for (int q = 0; q < NP / 4; ++q) {
        float4 v = fm[q];
        dm += fsn[4 * q] * v.x + fsn[4 * q + 1] * v.y + fsn[4 * q + 2] * v.z +
              fsn[4 * q + 3] * v.w;
    }
    float val = g_bd[b * NA + t] ? -1e30f : dm * 10.0f;
    float mx = fmaxf(pos, block_max_256(val, sh));
    float e = (val < -1e29f) ? 0.f : expf(val - mx);
    float ssum = block_sum_256(e, sh) + expf(pos - mx);
    if (t == 0) atomicAdd(&g_abcd_b[b], mx + logf(ssum) - pos);
}

__global__ void final_kernel(float* __restrict__ out) {
    int t = threadIdx.x;
    float per = 0.f, valid = 0.f;
    if (t < NB) {
        int c = g_cnt[t];
        per = g_abcd_b[t] / fmaxf((float)c, 1.0f);
        valid = (c > 0 && c < NA) ? 1.0f : 0.0f;
    }
    float pv = per * valid;
#pragma unroll
    for (int o = 16; o; o >>= 1) {
        pv += __shfl_down_sync(0xffffffffu, pv, o);
        valid += __shfl_down_sync(0xffffffffu, valid, o);
    }
    if (t == 0) {
        float gafd = g_gafd * (1.0f / (NB * NA * NP));
        float abcd = (valid > 0.f) ? pv / valid : 0.f;
        out[0] = gafd + 0.5f * abcd;
        out[1] = gafd;
        out[2] = abcd;
    }
}

// ---------------- host launch ----------------
extern "C" void kernel_launch(void* const* d_in, const int* in_sizes, int n_in,
                              void* d_out, int out_size) {
    const float* T = (const float*)d_in[0];
    const float* Sf = (const float*)d_in[1];
    const float* w1 = (const float*)d_in[2];
    const float* b1 = (const float*)d_in[3];
    const float* w2 = (const float*)d_in[4];
    const float* b2 = (const float*)d_in[5];
    const float* tw = (const float*)d_in[6];
    const float* tb = (const float*)d_in[7];
    const float* tg = (const float*)d_in[8];
    const float* tbe = (const float*)d_in[9];
    const float* sw = (const float*)d_in[10];
    const float* sb = (const float*)d_in[11];
    const float* sg = (const float*)d_in[12];
    const float* sbe = (const float*)d_in[13];
    float* out = (float*)d_out;

    const int DSMEM = NST * STG;  // 110592 per CTA, 2 CTAs/SM
    static int s_attr_done = 0;
    if (!s_attr_done) {
        cudaFuncSetAttribute(convmma_kernel,
                             cudaFuncAttributeMaxDynamicSharedMemorySize, DSMEM);
        s_attr_done = 1;
    }

    reset_kernel<<<(NB * HW + 255) / 256, 256>>>();
    tprep_kernel<<<dim3(128, 32, 16), dim3(32, 8)>>>(T);
    wprep_kernel<<<(9 * CM * CT + 255) / 256, 256>>>(w1);
    convmma_kernel<<<dim3(4, 32, 16), 256, DSMEM>>>(b1, w2);
    softplus_kernel<<<NB * HW / 256, 256>>>(b2, out);
    score_kernel<<<16, 256>>>();
    topk_kernel<<<16, 512>>>();
    gather_kernel<<<NB * NA, 256>>>(T, Sf);
    proj_kernel<CT><<<512, 256>>>(tw, tb, tg, tbe);
    proj_kernel<CS><<<512, 256>>>(sw, sb, sg, sbe);
    gafd_kernel<<<256, 256>>>();
    bd_kernel<<<NB, 256>>>();
    abcd_kernel<<<NB * NA, 256>>>();
    final_kernel<<<1, 32>>>(out);
}

// round 17
// speedup vs baseline: 2.4703x; 1.0062x over previous
#include <cuda_runtime.h>
#include <cuda_fp16.h>
#include <math.h>
#include <stdint.h>

#define NB 16
#define CT 1024
#define CS 512
#define CM 512
#define HH 64
#define WW 64
#define HW 4096
#define NP 256
#define NA 256

// ---------------- scratch (device globals; no allocation) ----------------
__device__ float g_heatacc[NB * HW];  // conv+1x1 fused accumulator
__device__ float g_heat[NB * HW];
__device__ float g_hsum[NB];
__device__ float g_score[NB * HW];
__device__ int   g_idx[NB * NA];
__device__ float g_sampT[NB * NA * CT];
__device__ float g_sampS[NB * NA * CS];
__device__ float g_sal[NB * NA];
__device__ float g_ft[NB * NA * NP];
__device__ float g_fs[NB * NA * NP];
__device__ int   g_bd[NB * NA];
__device__ int   g_cnt[NB];
__device__ float g_gafd;
__device__ float g_abcd_b[NB];

// fp16 pixel-major tensors (conv operand + coalesced gather source)
__device__ __align__(16) __half g_Thi[NB * HW * CT];      // [b][p][ci]
__device__ __align__(16) __half g_Shi[NB * HW * CS];      // [b][p][cs]
__device__ __align__(16) __half g_Whi[9 * CM * CT];       // [tap][co][ci]

// ---------------- sm_80-class PTX helpers (compile on compute_103) --------
__device__ __forceinline__ uint32_t smem_to_u32(const void* smem_ptr) {
    uint32_t addr;
    asm("{ .reg .u64 tmp; cvta.to.shared.u64 tmp, %1; cvt.u32.u64 %0, tmp; }"
        : "=r"(addr) : "l"(smem_ptr));
    return addr;
}
__device__ __forceinline__ void cp16(uint32_t dst, const void* src, bool ok) {
    int sz = ok ? 16 : 0;
    asm volatile("cp.async.cg.shared.global [%0], [%1], 16, %2;"
                 :: "r"(dst), "l"(src), "r"(sz) : "memory");
}
#define CP_COMMIT() asm volatile("cp.async.commit_group;" ::: "memory")
#define CP_WAIT1()  asm volatile("cp.async.wait_group 1;" ::: "memory")
#define CP_WAIT0()  asm volatile("cp.async.wait_group 0;" ::: "memory")

__device__ __forceinline__ void ldsm4(uint32_t* r, uint32_t addr) {
    asm volatile("ldmatrix.sync.aligned.m8n8.x4.shared.b16 {%0,%1,%2,%3}, [%4];"
                 : "=r"(r[0]), "=r"(r[1]), "=r"(r[2]), "=r"(r[3]) : "r"(addr));
}
// f32-accumulator fp16 MMA
__device__ __forceinline__ void mma_f32(float* c, const uint32_t* a,
                                        uint32_t b0, uint32_t b1) {
    asm volatile(
        "mma.sync.aligned.m16n8k16.row.col.f32.f16.f16.f32 "
        "{%0,%1,%2,%3}, {%4,%5,%6,%7}, {%8,%9}, {%0,%1,%2,%3};"
        : "+f"(c[0]), "+f"(c[1]), "+f"(c[2]), "+f"(c[3])
        : "r"(a[0]), "r"(a[1]), "r"(a[2]), "r"(a[3]), "r"(b0), "r"(b1));
}

// ---------------- generic helpers ----------------
__device__ __forceinline__ float block_sum_256(float v, float* sh) {
#pragma unroll
    for (int o = 16; o; o >>= 1) v += __shfl_down_sync(0xffffffffu, v, o);
    __syncthreads();
    if ((threadIdx.x & 31) == 0) sh[threadIdx.x >> 5] = v;
    __syncthreads();
    if (threadIdx.x == 0) {
        float t = 0.f;
        for (int i = 0; i < 8; ++i) t += sh[i];
        sh[32] = t;
    }
    __syncthreads();
    return sh[32];
}

__device__ __forceinline__ float block_max_256(float v, float* sh) {
#pragma unroll
    for (int o = 16; o; o >>= 1) v = fmaxf(v, __shfl_down_sync(0xffffffffu, v, o));
    __syncthreads();
    if ((threadIdx.x & 31) == 0) sh[threadIdx.x >> 5] = v;
    __syncthreads();
    if (threadIdx.x == 0) {
        float t = sh[0];
        for (int i = 1; i < 8; ++i) t = fmaxf(t, sh[i]);
        sh[32] = t;
    }
    __syncthreads();
    return sh[32];
}

__device__ __forceinline__ void threefry2x32(unsigned k0, unsigned k1,
                                             unsigned x0, unsigned x1,
                                             unsigned& o0, unsigned& o1) {
    unsigned ks[3] = {k0, k1, k0 ^ k1 ^ 0x1BD11BDAu};
    x0 += ks[0];
    x1 += ks[1];
    const int R[5][4] = {{13, 15, 26, 6}, {17, 29, 16, 24}, {13, 15, 26, 6},
                         {17, 29, 16, 24}, {13, 15, 26, 6}};
#pragma unroll
    for (int g = 0; g < 5; ++g) {
#pragma unroll
        for (int q = 0; q < 4; ++q) {
            x0 += x1;
            int rr = R[g][q];
            x1 = (x1 << rr) | (x1 >> (32 - rr));
            x1 ^= x0;
        }
        x0 += ks[(g + 1) % 3];
        x1 += ks[(g + 2) % 3] + (unsigned)(g + 1);
    }
    o0 = x0;
    o1 = x1;
}

// ---------------- kernels ----------------
__global__ void reset_kernel() {
    int i = blockIdx.x * blockDim.x + threadIdx.x;
    if (i < NB * HW) g_heatacc[i] = 0.f;
    if (i == 0) g_gafd = 0.f;
    if (i < NB) {
        g_abcd_b[i] = 0.f;
        g_hsum[i] = 0.f;
    }
}

// transpose + fp16 cast of teacher feat: T[b][ci][p] -> Thi[b][p][ci]
__global__ void tprep_kernel(const float* __restrict__ T) {
    __shared__ float tile[32][33];
    int b = blockIdx.z, p0 = blockIdx.x * 32, c0 = blockIdx.y * 32;
    int tx = threadIdx.x, ty = threadIdx.y;
    for (int i = ty; i < 32; i += 8)
        tile[i][tx] = T[((size_t)(b * CT + c0 + i)) * HW + p0 + tx];
    __syncthreads();
    for (int i = ty; i < 32; i += 8) {
        size_t o = ((size_t)b * HW + p0 + i) * CT + c0 + tx;
        g_Thi[o] = __float2half_rn(tile[tx][i]);
    }
}

// transpose + fp16 cast of student feat: Sf[b][cs][p] -> Shi[b][p][cs]
__global__ void sprep_kernel(const float* __restrict__ Sf) {
    __shared__ float tile[32][33];
    int b = blockIdx.z, p0 = blockIdx.x * 32, c0 = blockIdx.y * 32;
    int tx = threadIdx.x, ty = threadIdx.y;
    for (int i = ty; i < 32; i += 8)
        tile[i][tx] = Sf[((size_t)(b * CS + c0 + i)) * HW + p0 + tx];
    __syncthreads();
    for (int i = ty; i < 32; i += 8) {
        size_t o = ((size_t)b * HW + p0 + i) * CS + c0 + tx;
        g_Shi[o] = __float2half_rn(tile[tx][i]);
    }
}

// weights: W1[co][ci][tap] -> Whi[tap][co][ci] (fp16 rn)
__global__ void wprep_kernel(const float* __restrict__ W1) {
    int idx = blockIdx.x * blockDim.x + threadIdx.x;
    if (idx >= 9 * CM * CT) return;
    int ci = idx & (CT - 1);
    int rest = idx >> 10;
    int co = rest & (CM - 1);
    int tap = rest >> 9;
    g_Whi[idx] = __float2half_rn(W1[((size_t)co * CT + ci) * 9 + tap]);
}

// conv1 (pure fp16 implicit GEMM, f32 acc) fused with the 1x1 conv.
// CTA: 256 threads, 128 px x 128 co; 3-stage cp.async, single sync/chunk,
// 2 CTAs per SM (anti-phased), hoisted u32 address bases.
#define ROWB 144                      // bytes per smem row (64 fp16 + 8 pad)
#define AT_BYTES (128 * ROWB)         // 18432
#define STG (2 * AT_BYTES)            // A + B = 36864
#define NST 3
__global__ __launch_bounds__(256, 2)
void convmma_kernel(const float* __restrict__ b1, const float* __restrict__ w2) {
    extern __shared__ char dsm[];
    uint32_t sb = smem_to_u32(dsm);
    int tid = threadIdx.x, lane = tid & 31, wid = tid >> 5;
    int co0 = blockIdx.x * 128;
    int pixtile = blockIdx.y;
    int bb = blockIdx.z;
    int y0 = pixtile * 2, p0 = pixtile * 128;
    int wm = wid & 3, wn = wid >> 2;   // 4 M-groups of 32 px; 2 N-groups of 64 co

    float acc[2][8][4];
#pragma unroll
    for (int i = 0; i < 2; ++i)
#pragma unroll
        for (int j = 0; j < 8; ++j)
#pragma unroll
            for (int k = 0; k < 4; ++k) acc[i][j][k] = 0.f;

    // hoisted per-thread load state (u32 element bases)
    uint32_t aoff[4], agbase[4], bgbase[4];
    int ays[4], axs[4];
#pragma unroll
    for (int i = 0; i < 4; ++i) {
        int u = i * 256 + tid;
        int r = u >> 3, seg = u & 7;
        int ys0 = y0 + (r >> 6), xs0 = r & 63;
        ays[i] = ys0;
        axs[i] = xs0;
        agbase[i] = (uint32_t)((bb * HW + ys0 * 64 + xs0) * CT + seg * 8);
        aoff[i] = (uint32_t)(r * ROWB + seg * 16);
        bgbase[i] = (uint32_t)((co0 + r) * CT + seg * 8);
    }

    auto load_chunk = [&](int c, int s) {
        int tap = c >> 4, kc = c & 15;
        int dy = tap / 3 - 1, dx = tap % 3 - 1;
        uint32_t ci0 = (uint32_t)(kc * 64);
        uint32_t deltaA = (uint32_t)((dy * 64 + dx) * CT) + ci0;  // mod-2^32 ok
        uint32_t deltaB = (uint32_t)(tap * CM * CT) + ci0;
        uint32_t base = sb + (uint32_t)s * STG;
#pragma unroll
        for (int i = 0; i < 4; ++i) {
            bool ok = ((unsigned)(ays[i] + dy) < 64u) &&
                      ((unsigned)(axs[i] + dx) < 64u);
            uint32_t d = ok ? deltaA : ci0;  // !ok: valid fallback addr, sz=0
            cp16(base + aoff[i], g_Thi + (agbase[i] + d), ok);
        }
#pragma unroll
        for (int i = 0; i < 4; ++i)
            cp16(base + AT_BYTES + aoff[i], g_Whi + (bgbase[i] + deltaB), true);
    };

    auto compute = [&](int s) {
        uint32_t Ah = sb + (uint32_t)s * STG;
        uint32_t Bh = Ah + AT_BYTES;
#pragma unroll
        for (int ks = 0; ks < 4; ++ks) {
            uint32_t aH[2][4];
#pragma unroll
            for (int t = 0; t < 2; ++t) {
                uint32_t ra = (uint32_t)((wm * 32 + t * 16 + (lane & 15)) * ROWB +
                                         ks * 32 + (lane >> 4) * 16);
                ldsm4(aH[t], Ah + ra);
            }
#pragma unroll
            for (int nt = 0; nt < 4; ++nt) {
                uint32_t rb = (uint32_t)((wn * 64 + nt * 16 + (lane & 15)) * ROWB +
                                         ks * 32 + (lane >> 4) * 16);
                uint32_t bb4[4];
                ldsm4(bb4, Bh + rb);
#pragma unroll
                for (int mi = 0; mi < 2; ++mi) {
                    mma_f32(acc[mi][2 * nt], aH[mi], bb4[0], bb4[2]);
                    mma_f32(acc[mi][2 * nt + 1], aH[mi], bb4[1], bb4[3]);
                }
            }
        }
    };

    // prologue: 2 stages in flight
    load_chunk(0, 0);
    CP_COMMIT();
    load_chunk(1, 1);
    CP_COMMIT();
#pragma unroll 1
    for (int c = 0; c < 144; ++c) {
        int s = c % NST;
        if (c + 2 < 144) CP_WAIT1();
        else CP_WAIT0();
        __syncthreads();     // chunk c visible + compute(c-1) done -> stage free
        if (c + 2 < 144) {
            load_chunk(c + 2, (c + 2) % NST);
            CP_COMMIT();
        }
        compute(s);
    }

    // fused epilogue: h = relu(acc + b1); heatacc[p] += sum_co h * w2[co]
    float hp[2][2] = {{0.f, 0.f}, {0.f, 0.f}};
#pragma unroll
    for (int mi = 0; mi < 2; ++mi) {
#pragma unroll
        for (int nt = 0; nt < 8; ++nt) {
            int co = co0 + wn * 64 + nt * 8 + (lane & 3) * 2;
            float bv0 = b1[co], bv1 = b1[co + 1];
            float w20 = w2[co], w21 = w2[co + 1];
            float h00 = fmaxf(acc[mi][nt][0] + bv0, 0.f);
            float h01 = fmaxf(acc[mi][nt][1] + bv1, 0.f);
            float h10 = fmaxf(acc[mi][nt][2] + bv0, 0.f);
            float h11 = fmaxf(acc[mi][nt][3] + bv1, 0.f);
            hp[mi][0] += h00 * w20 + h01 * w21;
            hp[mi][1] += h10 * w20 + h11 * w21;
        }
    }
#pragma unroll
    for (int mi = 0; mi < 2; ++mi) {
        int r0 = wm * 32 + mi * 16 + (lane >> 2);
        atomicAdd(&g_heatacc[bb * HW + p0 + r0], hp[mi][0]);
        atomicAdd(&g_heatacc[bb * HW + p0 + r0 + 8], hp[mi][1]);
    }
}

// softplus(acc + b2) -> heatmap; also per-batch sum via block reduce + atomic
__global__ void softplus_kernel(const float* __restrict__ b2,
                                float* __restrict__ out) {
    __shared__ float sh[33];
    int i = blockIdx.x * 256 + threadIdx.x;
    float a = g_heatacc[i] + b2[0];
    float sp = fmaxf(a, 0.f) + log1pf(expf(-fabsf(a)));
    g_heat[i] = sp;
    out[3 + i] = sp;
    float bs = block_sum_256(sp, sh);
    if (threadIdx.x == 0) atomicAdd(&g_hsum[i >> 12], bs);
}

// fully parallel score: log(prob) + JAX (partitionable threefry) Gumbel
__global__ void score_kernel() {
    int i = blockIdx.x * 256 + threadIdx.x;
    int b = i >> 12;
    float S = g_hsum[b];
    unsigned gi = (unsigned)i;
    unsigned o0, o1;
    threefry2x32(0u, 42u, 0u, gi, o0, o1);
    unsigned bits = o0 ^ o1;
    float f = __uint_as_float((bits >> 9) | 0x3f800000u) - 1.0f;
    float u = fmaxf(1e-8f, f * (1.0f - 1e-8f) + 1e-8f);
    float gum = -logf(-logf(u));
    g_score[i] = logf(g_heat[i] / (S + 1e-6f) + 1e-12f) + gum;
}

// top-256 per batch via in-smem bitonic sort
__global__ void topk_kernel() {
    __shared__ float key[HW];
    __shared__ int val[HW];
    int b = blockIdx.x;
    for (int i = threadIdx.x; i < HW; i += blockDim.x) {
        key[i] = -g_score[b * HW + i];
        val[i] = i;
    }
    for (int k = 2; k <= HW; k <<= 1)
        for (int j = k >> 1; j > 0; j >>= 1) {
            __syncthreads();
            for (int i = threadIdx.x; i < HW; i += blockDim.x) {
                int p = i ^ j;
                if (p > i) {
                    bool up = ((i & k) == 0);
                    float ki = key[i], kp = key[p];
                    if ((ki > kp) == up) {
                        key[i] = kp;
                        key[p] = ki;
                        int t = val[i];
                        val[i] = val[p];
                        val[p] = t;
                    }
                }
            }
        }
    __syncthreads();
    for (int i = threadIdx.x; i < NA; i += blockDim.x) g_idx[b * NA + i] = val[i];
}

// bilinear sample == 0.25 * sum of 4 pixels, zero pad.
// Teacher/student read from pixel-major fp16 copies -> fully coalesced.
__global__ void gather_kernel() {
    int blk = blockIdx.x;
    int b = blk >> 8, n = blk & 255;
    int idx = g_idx[b * NA + n];
    int r = idx >> 6, c = idx & 63;
    bool rv = r > 0, cv = c > 0;
    int o11 = idx, o10 = idx - 1, o01 = idx - WW, o00 = idx - WW - 1;

    // teacher: 4 channels per thread (CT=1024, 256 threads)
    {
        const __half* tb = g_Thi + (size_t)(b * HW) * CT;
        int t4 = threadIdx.x * 4;
        float s0 = 0.f, s1 = 0.f, s2 = 0.f, s3 = 0.f;
        auto addp = [&](int off) {
            const __half2* p = (const __half2*)(tb + (size_t)off * CT + t4);
            __half2 v0 = p[0], v1 = p[1];
            s0 += __low2float(v0);
            s1 += __high2float(v0);
            s2 += __low2float(v1);
            s3 += __high2float(v1);
        };
        addp(o11);
        if (cv) addp(o10);
        if (rv) {
            addp(o01);
            if (cv) addp(o00);
        }
        *(float4*)&g_sampT[(size_t)(b * NA + n) * CT + t4] =
            make_float4(0.25f * s0, 0.25f * s1, 0.25f * s2, 0.25f * s3);
    }
    // student: 2 channels per thread (CS=512)
    {
        const __half* sbp = g_Shi + (size_t)(b * HW) * CS;
        int t2 = threadIdx.x * 2;
        float s0 = 0.f, s1 = 0.f;
        auto addp = [&](int off) {
            __half2 v = *(const __half2*)(sbp + (size_t)off * CS + t2);
            s0 += __low2float(v);
            s1 += __high2float(v);
        };
        addp(o11);
        if (cv) addp(o10);
        if (rv) {
            addp(o01);
            if (cv) addp(o00);
        }
        *(float2*)&g_sampS[(size_t)(b * NA + n) * CS + t2] =
            make_float2(0.25f * s0, 0.25f * s1);
    }
    if (threadIdx.x == 0) {
        const float* base = g_heat + b * HW;
        float s = base[o11];
        if (cv) s += base[o10];
        if (rv) {
            s += base[o01];
            if (cv) s += base[o00];
        }
        g_sal[b * NA + n] = 0.25f * s;
    }
}

// [rows,C]@[C,256] + bias -> LayerNorm -> l2norm. 8 rows per block, thread = p.
template <int C>
__global__ void proj_kernel(const float* __restrict__ wmat,
                            const float* __restrict__ bias,
                            const float* __restrict__ gamma,
                            const float* __restrict__ beta) {
    __shared__ float sRow[8 * C];
    __shared__ float sh[33];
    const float* samp = (C == CT) ? g_sampT : g_sampS;
    float* outp = (C == CT) ? g_ft : g_fs;
    int a0 = blockIdx.x * 8;
    int p = threadIdx.x;
    for (int i = threadIdx.x; i < 8 * C; i += 256) sRow[i] = samp[(size_t)a0 * C + i];
    __syncthreads();
    float acc[8];
#pragma unroll
    for (int i = 0; i < 8; ++i) acc[i] = 0.f;
    for (int c = 0; c < C; ++c) {
        float w = wmat[(size_t)c * NP + p];
#pragma unroll
        for (int i = 0; i < 8; ++i) acc[i] += sRow[i * C + c] * w;
    }
    float bi = bias[p], ga = gamma[p], be = beta[p];
#pragma unroll 1
    for (int i = 0; i < 8; ++i) {
        float x = acc[i] + bi;
        float mu = block_sum_256(x, sh) * (1.0f / NP);
        float d = x - mu;
        float var = block_sum_256(d * d, sh) * (1.0f / NP);
        float y = d * rsqrtf(var + 1e-5f) * ga + be;
        float nrm = sqrtf(block_sum_256(y * y, sh));
        y = y / fmaxf(nrm, 1e-12f);
        outp[(size_t)(a0 + i) * NP + p] = y;
    }
}

__global__ void gafd_kernel() {
    __shared__ float sh[33];
    float s = 0.f;
    const int total = NB * NA * NP;
    for (int i = blockIdx.x * blockDim.x + threadIdx.x; i < total;
         i += gridDim.x * blockDim.x) {
        float d = g_fs[i] - g_ft[i];
        s += d * d;
    }
    float bs = block_sum_256(s, sh);
    if (threadIdx.x == 0) atomicAdd(&g_gafd, bs);
}

__global__ void bd_kernel() {
    __shared__ float sh[33];
    int b = blockIdx.x;
    float s = g_sal[b * NA + threadIdx.x];
    float mx = block_max_256(s, sh);
    int bd = (s > 0.6f * mx) ? 1 : 0;
    g_bd[b * NA + threadIdx.x] = bd;
    float cnt = block_sum_256((float)bd, sh);
    if (threadIdx.x == 0) g_cnt[b] = (int)(cnt + 0.5f);
}

__global__ void abcd_kernel() {
    __shared__ float fsn[NP];
    __shared__ float sh[33];
    int blk = blockIdx.x;
    int b = blk >> 8, n = blk & 255;
    if (!g_bd[b * NA + n]) return;
    int t = threadIdx.x;
    float fv = g_fs[(size_t)(b * NA + n) * NP + t];
    float ftv = g_ft[(size_t)(b * NA + n) * NP + t];
    fsn[t] = fv;
    __syncthreads();
    float pos = block_sum_256(fv * ftv, sh) * 10.0f;  // /TAU
    const float4* fm = (const float4*)(g_fs + (size_t)(b * NA + t) * NP);
    float dm = 0.f;
#pragma unroll 4
    for (int q = 0; q < NP / 4; ++q) {
        float4 v = fm[q];
        dm += fsn[4 * q] * v.x + fsn[4 * q + 1] * v.y + fsn[4 * q + 2] * v.z +
              fsn[4 * q + 3] * v.w;
    }
    float val = g_bd[b * NA + t] ? -1e30f : dm * 10.0f;
    float mx = fmaxf(pos, block_max_256(val, sh));
    float e = (val < -1e29f) ? 0.f : expf(val - mx);
    float ssum = block_sum_256(e, sh) + expf(pos - mx);
    if (t == 0) atomicAdd(&g_abcd_b[b], mx + logf(ssum) - pos);
}

__global__ void final_kernel(float* __restrict__ out) {
    int t = threadIdx.x;
    float per = 0.f, valid = 0.f;
    if (t < NB) {
        int c = g_cnt[t];
        per = g_abcd_b[t] / fmaxf((float)c, 1.0f);
        valid = (c > 0 && c < NA) ? 1.0f : 0.0f;
    }
    float pv = per * valid;
#pragma unroll
    for (int o = 16; o; o >>= 1) {
        pv += __shfl_down_sync(0xffffffffu, pv, o);
        valid += __shfl_down_sync(0xffffffffu, valid, o);
    }
    if (t == 0) {
        float gafd = g_gafd * (1.0f / (NB * NA * NP));
        float abcd = (valid > 0.f) ? pv / valid : 0.f;
        out[0] = gafd + 0.5f * abcd;
        out[1] = gafd;
        out[2] = abcd;
    }
}

// ---------------- host launch ----------------
extern "C" void kernel_launch(void* const* d_in, const int* in_sizes, int n_in,
                              void* d_out, int out_size) {
    const float* T = (const float*)d_in[0];
    const float* Sf = (const float*)d_in[1];
    const float* w1 = (const float*)d_in[2];
    const float* b1 = (const float*)d_in[3];
    const float* w2 = (const float*)d_in[4];
    const float* b2 = (const float*)d_in[5];
    const float* tw = (const float*)d_in[6];
    const float* tb = (const float*)d_in[7];
    const float* tg = (const float*)d_in[8];
    const float* tbe = (const float*)d_in[9];
    const float* sw = (const float*)d_in[10];
    const float* sb = (const float*)d_in[11];
    const float* sg = (const float*)d_in[12];
    const float* sbe = (const float*)d_in[13];
    float* out = (float*)d_out;

    const int DSMEM = NST * STG;  // 110592 per CTA, 2 CTAs/SM
    static int s_attr_done = 0;
    if (!s_attr_done) {
        cudaFuncSetAttribute(convmma_kernel,
                             cudaFuncAttributeMaxDynamicSharedMemorySize, DSMEM);
        s_attr_done = 1;
    }

    reset_kernel<<<(NB * HW + 255) / 256, 256>>>();
    tprep_kernel<<<dim3(128, 32, 16), dim3(32, 8)>>>(T);
    sprep_kernel<<<dim3(128, 16, 16), dim3(32, 8)>>>(Sf);
    wprep_kernel<<<(9 * CM * CT + 255) / 256, 256>>>(w1);
    convmma_kernel<<<dim3(4, 32, 16), 256, DSMEM>>>(b1, w2);
    softplus_kernel<<<NB * HW / 256, 256>>>(b2, out);
    score_kernel<<<NB * HW / 256, 256>>>();
    topk_kernel<<<16, 512>>>();
    gather_kernel<<<NB * NA, 256>>>();
    proj_kernel<CT><<<512, 256>>>(tw, tb, tg, tbe);
    proj_kernel<CS><<<512, 256>>>(sw, sb, sg, sbe);
    gafd_kernel<<<256, 256>>>();
    bd_kernel<<<NB, 256>>>();
    abcd_kernel<<<NB * NA, 256>>>();
    final_kernel<<<1, 32>>>(out);
}